// round 12
// baseline (speedup 1.0000x reference)
#include <cuda_runtime.h>
#include <cuda_fp16.h>
#include <cstdint>

#define DV 128
#define NSTEP 10
#define BSZ 4096
#define CNT0 20000
#define CNT1 2000
#define CNT2 15000
#define ROWS_TOT (CNT0 + CNT1 + CNT2)
#define T1PAD 2048   // type-1 node count padded to tile multiple

typedef unsigned long long u64;

__device__ __align__(16) float g_P[2 * ROWS_TOT * DV];          // x@Wih^T + bih + bhh
__device__ __align__(16) float g_aggC[6 * BSZ * DV];            // c-set RNN means  [lay*3+nt][b]
__device__ __align__(16) float g_aggT[6 * T1PAD * DV];          // type-1 RNN means [lay*3+nt][node]
__device__ __align__(16) float g_attnT[T1PAD * DV];             // type-1 attention output per node

static __device__ __forceinline__ float tanh_fast(float x){
  float e = __expf(2.0f * x);
  return 1.0f - __fdividef(2.0f, e + 1.0f);
}
static __device__ __forceinline__ uint32_t tf32b(float v){
  uint32_t b;
  asm("cvt.rna.tf32.f32 %0, %1;" : "=r"(b) : "f"(v));
  return b;
}
static __device__ __forceinline__ uint32_t h2pack(float a, float b){
  __half2 h = __floats2half2_rn(a, b);
  return *(uint32_t*)&h;
}
// m16n8k8 tf32 HMMA (precompute kernel)
static __device__ __forceinline__ void mma_tf32(float* c,
    uint32_t a0, uint32_t a1, uint32_t a2, uint32_t a3, uint32_t b0, uint32_t b1){
  asm volatile("mma.sync.aligned.m16n8k8.row.col.f32.tf32.tf32.f32 "
    "{%0,%1,%2,%3}, {%4,%5,%6,%7}, {%8,%9}, {%0,%1,%2,%3};"
    : "+f"(c[0]), "+f"(c[1]), "+f"(c[2]), "+f"(c[3])
    : "r"(a0), "r"(a1), "r"(a2), "r"(a3), "r"(b0), "r"(b1));
}
// m16n8k16 fp16 HMMA, f32 accumulate (rnn kernel): A 16x16 row, B 16x8 col
static __device__ __forceinline__ void mma_f16(float* c,
    uint32_t a0, uint32_t a1, uint32_t a2, uint32_t a3, uint32_t b0, uint32_t b1){
  asm volatile("mma.sync.aligned.m16n8k16.row.col.f32.f16.f16.f32 "
    "{%0,%1,%2,%3}, {%4,%5,%6,%7}, {%8,%9}, {%0,%1,%2,%3};"
    : "+f"(c[0]), "+f"(c[1]), "+f"(c[2]), "+f"(c[3])
    : "r"(a0), "r"(a1), "r"(a2), "r"(a3), "r"(b0), "r"(b1));
}

// ---------------------------------------------------------------------------
// Kernel 1 (unchanged from R9 win): P = emb @ Wih^T + biases, HMMA tf32.
// One block = 2 layers x 2 row-tiles.
// ---------------------------------------------------------------------------
#define PXB 32768
#define P_SMEM_BYTES ((32768 + 17408) * 4)

__global__ void __launch_bounds__(512, 1) precompute_P_kernel(
    const float* __restrict__ emb0, const float* __restrict__ emb1, const float* __restrict__ emb2,
    const float* __restrict__ Wih, const float* __restrict__ bih, const float* __restrict__ bhh)
{
  extern __shared__ float smf[];
  float* XB = smf + PXB;
  float* OT = smf + PXB;      // alias (phases separated by syncs)

  const int tid  = threadIdx.x;
  const int w    = tid >> 5;
  const int lane = tid & 31;
  const int g    = lane >> 2;
  const int t    = lane & 3;

  int xb = blockIdx.x, nt, tile0, rows;
  if (xb < 79)      { nt = 0; tile0 = xb * 2;        rows = CNT0; }
  else if (xb < 87) { nt = 1; tile0 = (xb - 79) * 2; rows = CNT1; }
  else              { nt = 2; tile0 = (xb - 87) * 2; rows = CNT2; }
  const float* emb = (nt == 0) ? emb0 : ((nt == 1) ? emb1 : emb2);

  for (int idx = tid; idx < 8192; idx += 512){
    int ll  = idx & 31;
    int kc  = (idx >> 5) & 15;
    int jsb = (idx >> 9) & 7;
    int lay = idx >> 12;
    const float* Wb = Wih + (size_t)(lay * 3 + nt) * DV * DV;
    int gg = ll >> 2, tt = ll & 3;
    int j = 16 * jsb + gg, k = 8 * kc + tt;
    uint4 hi;
    hi.x = tf32b(Wb[j * DV + k]);
    hi.y = tf32b(Wb[(j + 8) * DV + k]);
    hi.z = tf32b(Wb[j * DV + k + 4]);
    hi.w = tf32b(Wb[(j + 8) * DV + k + 4]);
    *(uint4*)&smf[lay * 16384 + (jsb * 16 + kc) * 128 + ll * 4] = hi;
  }

  const int js = w & 7;
  const int j0 = js << 4;
  const int m0base = (w >> 3) << 6;

  #pragma unroll
  for (int sub = 0; sub < 2; sub++){
    const int row0 = (tile0 + sub) * 128;
    if (row0 >= rows) break;

    __syncthreads();

    {
      uint32_t* XBu = (uint32_t*)XB;
      for (int idx = tid; idx < 4096; idx += 512){
        int m = idx >> 5, q = idx & 31;
        int gr = row0 + m;
        float4 v = make_float4(0.f, 0.f, 0.f, 0.f);
        if (gr < rows) v = *(const float4*)(emb + (size_t)gr * DV + 4 * q);
        const float* ve = (const float*)&v;
        #pragma unroll
        for (int e = 0; e < 4; e++){
          int k = 4 * q + e;
          XBu[((k >> 3) * 128 + m) * 8 + (k & 3) * 2 + ((k >> 2) & 1)] = tf32b(ve[e]);
        }
      }
    }
    __syncthreads();

    float c0[8][4], c1[8][4];
    #pragma unroll
    for (int mt = 0; mt < 8; mt++)
      #pragma unroll
      for (int q = 0; q < 4; q++){ c0[mt][q] = 0.0f; c1[mt][q] = 0.0f; }

    #pragma unroll 2
    for (int kc = 0; kc < 16; kc++){
      uint4 A0 = *(const uint4*)&smf[(js * 16 + kc) * 128 + lane * 4];
      uint4 A1 = *(const uint4*)&smf[16384 + (js * 16 + kc) * 128 + lane * 4];
      #pragma unroll
      for (int mt = 0; mt < 8; mt++){
        float2 b = *(const float2*)&XB[(kc * 128 + m0base + 8 * mt + g) * 8 + t * 2];
        uint32_t b0 = __float_as_uint(b.x), b1 = __float_as_uint(b.y);
        mma_tf32(c0[mt], A0.x, A0.y, A0.z, A0.w, b0, b1);
        mma_tf32(c1[mt], A1.x, A1.y, A1.z, A1.w, b0, b1);
      }
    }
    __syncthreads();

    #pragma unroll
    for (int lay = 0; lay < 2; lay++){
      const int comb = lay * 3 + nt;
      const float bj0 = bih[(size_t)comb * DV + j0 + g]     + bhh[(size_t)comb * DV + j0 + g];
      const float bj8 = bih[(size_t)comb * DV + j0 + g + 8] + bhh[(size_t)comb * DV + j0 + g + 8];
      float (*c)[4] = lay ? c1 : c0;
      #pragma unroll
      for (int mt = 0; mt < 8; mt++){
        int m0 = m0base + 8 * mt;
        OT[(m0 + 2 * t    ) * 136 + j0 + g    ] = c[mt][0] + bj0;
        OT[(m0 + 2 * t + 1) * 136 + j0 + g    ] = c[mt][1] + bj0;
        OT[(m0 + 2 * t    ) * 136 + j0 + g + 8] = c[mt][2] + bj8;
        OT[(m0 + 2 * t + 1) * 136 + j0 + g + 8] = c[mt][3] + bj8;
      }
      __syncthreads();
      const size_t Poff = (size_t)lay * ROWS_TOT * DV
                        + (size_t)((nt == 0) ? 0 : ((nt == 1) ? CNT0 : (CNT0 + CNT1))) * DV;
      for (int idx = tid; idx < 4096; idx += 512){
        int m = idx >> 5, q = idx & 31;
        int gr = row0 + m;
        if (gr < rows)
          *(float4*)(g_P + Poff + (size_t)gr * DV + 4 * q) = *(const float4*)&OT[m * 136 + 4 * q];
      }
      if (lay == 0) __syncthreads();
    }
  }
}

// ---------------------------------------------------------------------------
// Kernel 2: RNN via fp16 m16n8k16 HMMA. ONE 64-row m-half per 256-thread
// block (halves are fully independent) -> 68.1KB smem, 3 blocks/SM,
// 576 blocks = 1.30 waves. MMA split in two mt-chunks of 4 to fit the
// 85-reg cap of launch_bounds(256,3). Numerics identical to R11.
// smem: WF 32KB | HP 2x16KB | nids 2.5KB = 68,096 B
// ---------------------------------------------------------------------------
#define RHP_F 8192                       // float offset of HP
#define RNID_F 16384
#define RNN_SMEM_BYTES ((16384 + 640) * 4)

__global__ void __launch_bounds__(256, 3) rnn_mma_kernel(
    const float* __restrict__ Whh,
    const int* __restrict__ c_ids,
    const int* __restrict__ n00, const int* __restrict__ n01, const int* __restrict__ n02,
    const int* __restrict__ n10, const int* __restrict__ n11, const int* __restrict__ n12)
{
  extern __shared__ float smf[];
  uint4* WF4 = (uint4*)smf;                    // fp16 A fragments (32KB)
  char*  HPc = (char*)(smf + RHP_F);           // 2 x 16KB fp16 h buffers (64 rows)
  int* nidsh = (int*)(smf + RNID_F);           // 64 x 10

  const int tid  = threadIdx.x;
  const int w    = tid >> 5;                   // 0..7
  const int lane = tid & 31;
  const int g    = lane >> 2;
  const int t    = lane & 3;

  const int y    = blockIdx.y;      // lay*3 + nt
  const int lay  = y / 3;
  const int nt   = y % 3;
  const int xb   = blockIdx.x;      // 0..95
  const int tile = xb >> 1;
  const int half = xb & 1;
  const bool isT = (tile >= 32);
  const int ntype = isT ? 1 : 0;
  const int mrow0 = (isT ? (tile - 32) : tile) * 128 + (half << 6);  // 64 rows
  const int nsel = ntype * 3 + nt;
  const int* ntab = (nsel == 0) ? n00 : (nsel == 1) ? n01 : (nsel == 2) ? n02
                  : (nsel == 3) ? n10 : (nsel == 4) ? n11 : n12;
  const float* Wb = Whh + (size_t)(lay * 3 + nt) * DV * DV;
  const float* Pb = g_P + (size_t)lay * ROWS_TOT * DV
                  + (size_t)((nt == 0) ? 0 : ((nt == 1) ? CNT0 : (CNT0 + CNT1))) * DV;

  // fp16 W fragments: entry = (jsb, kc, lane) -> a0..a3
  for (int idx = tid; idx < 2048; idx += 256){
    int ll  = idx & 31;
    int kc  = (idx >> 5) & 7;
    int jsb = idx >> 8;
    int gg = ll >> 2, tt = ll & 3;
    int j = 16 * jsb + gg, k = 16 * kc + 2 * tt;
    uint4 A;
    A.x = h2pack(Wb[j * DV + k],           Wb[j * DV + k + 1]);
    A.y = h2pack(Wb[(j + 8) * DV + k],     Wb[(j + 8) * DV + k + 1]);
    A.z = h2pack(Wb[j * DV + k + 8],       Wb[j * DV + k + 9]);
    A.w = h2pack(Wb[(j + 8) * DV + k + 8], Wb[(j + 8) * DV + k + 9]);
    WF4[(jsb * 8 + kc) * 32 + ll] = A;
  }
  for (int idx = tid; idx < 64 * NSTEP; idx += 256){
    int r = idx / NSTEP, s = idx % NSTEP;
    int id = isT ? min(mrow0 + r, CNT1 - 1) : c_ids[mrow0 + r];
    nidsh[idx] = ntab[(size_t)id * NSTEP + s];
  }
  __syncthreads();

  const int js = w;                 // 8 j-stripes of 16
  const int j0 = js << 4;

  float hsum[8][4];
  #pragma unroll
  for (int mt = 0; mt < 8; mt++)
    #pragma unroll
    for (int q = 0; q < 4; q++) hsum[mt][q] = 0.0f;

  for (int s = 0; s < NSTEP; s++){
    char* HPr = HPc + (((s + 1) & 1) << 14);
    char* HPw = HPc + ((s & 1) << 14);
    __half* HW = (__half*)HPw;

    #pragma unroll
    for (int ch = 0; ch < 2; ch++){
      // prefetch P for this chunk's 4 m-tiles (hidden under chunk MMA)
      float pf[4][4];
      #pragma unroll
      for (int mtl = 0; mtl < 4; mtl++){
        int m0 = 8 * (4 * ch + mtl);
        int nv0 = nidsh[(m0 + 2 * t) * NSTEP + s];
        int nv1 = nidsh[(m0 + 2 * t + 1) * NSTEP + s];
        const float* P0 = Pb + (size_t)nv0 * DV;
        const float* P1 = Pb + (size_t)nv1 * DV;
        pf[mtl][0] = P0[j0 + g];     pf[mtl][1] = P1[j0 + g];
        pf[mtl][2] = P0[j0 + g + 8]; pf[mtl][3] = P1[j0 + g + 8];
      }

      float c[4][4];
      #pragma unroll
      for (int mtl = 0; mtl < 4; mtl++)
        #pragma unroll
        for (int q = 0; q < 4; q++) c[mtl][q] = 0.0f;

      if (s > 0){
        #pragma unroll
        for (int kc = 0; kc < 8; kc++){
          uint4 A = WF4[(js * 8 + kc) * 32 + lane];
          #pragma unroll
          for (int mtl = 0; mtl < 4; mtl++){
            int m0 = 8 * (4 * ch + mtl);
            uint2 b = *(const uint2*)(HPr + ((size_t)((kc * 64 + m0 + g) * 4 + t) << 3));
            mma_f16(c[mtl], A.x, A.y, A.z, A.w, b.x, b.y);
          }
        }
      }

      #pragma unroll
      for (int mtl = 0; mtl < 4; mtl++){
        int m0 = 8 * (4 * ch + mtl);
        float v0 = tanh_fast(c[mtl][0] + pf[mtl][0]);   // (j0+g,   m0+2t)
        float v1 = tanh_fast(c[mtl][1] + pf[mtl][1]);   // (j0+g,   m0+2t+1)
        float v2 = tanh_fast(c[mtl][2] + pf[mtl][2]);   // (j0+g+8, m0+2t)
        float v3 = tanh_fast(c[mtl][3] + pf[mtl][3]);   // (j0+g+8, m0+2t+1)
        int mt = 4 * ch + mtl;
        hsum[mt][0] += v0; hsum[mt][1] += v1; hsum[mt][2] += v2; hsum[mt][3] += v3;
        // h -> fp16 pair layout (64-row stripes): kc'=js
        int i0 = js * 1024 + (m0 + 2 * t) * 16 + (g >> 1) * 4 + (g & 1);
        HW[i0]      = __float2half_rn(v0);
        HW[i0 + 2]  = __float2half_rn(v2);
        HW[i0 + 16] = __float2half_rn(v1);
        HW[i0 + 18] = __float2half_rn(v3);
      }
    }
    __syncthreads();   // h_s visible to all warps for next step's MMA
  }

  // mean-transpose via float alias over both HP buffers (spans all warps' bytes)
  __syncthreads();
  float* HT = smf + RHP_F;          // 64 x 128 floats = 32KB
  const float inv = 1.0f / NSTEP;
  #pragma unroll
  for (int mt = 0; mt < 8; mt++){
    int m0 = 8 * mt;
    HT[(m0 + 2 * t    ) * 128 + j0 + g    ] = hsum[mt][0] * inv;
    HT[(m0 + 2 * t + 1) * 128 + j0 + g    ] = hsum[mt][1] * inv;
    HT[(m0 + 2 * t    ) * 128 + j0 + g + 8] = hsum[mt][2] * inv;
    HT[(m0 + 2 * t + 1) * 128 + j0 + g + 8] = hsum[mt][3] * inv;
  }
  __syncthreads();
  float* ob = isT ? (g_aggT + ((size_t)y * T1PAD + mrow0) * DV)
                  : (g_aggC + ((size_t)y * BSZ  + mrow0) * DV);
  for (int idx = tid; idx < 2048; idx += 256){
    int m = idx >> 5;
    int q = idx & 31;
    ((float4*)ob)[m * 32 + q] = *(const float4*)&HT[m * 128 + 4 * q];
  }
}

// ---------------------------------------------------------------------------
// Kernel 3: attention (deduped; unchanged).
// ---------------------------------------------------------------------------
static __device__ __forceinline__ float breduce128(float v, float* sh){
  #pragma unroll
  for (int o = 16; o > 0; o >>= 1) v += __shfl_xor_sync(0xffffffffu, v, o);
  if ((threadIdx.x & 31) == 0) sh[threadIdx.x >> 5] = v;
  __syncthreads();
  float r = sh[0] + sh[1] + sh[2] + sh[3];
  __syncthreads();
  return r;
}

__global__ void __launch_bounds__(128) attn_kernel(
    const float* __restrict__ emb0, const float* __restrict__ emb1,
    const int* __restrict__ c_ids,
    const float* __restrict__ attW, float* __restrict__ out)
{
  __shared__ float sh[4];
  const int b  = blockIdx.x;
  const int d  = threadIdx.x;
  const bool isT = (b >= BSZ);
  const int node = b - BSZ;
  if (isT && node >= CNT1) return;
  const int ntype = isT ? 1 : 0;
  const float* agg = isT ? g_aggT : g_aggC;
  const int nrows  = isT ? T1PAD : BSZ;
  const int ridx   = isT ? node : b;
  float cur = isT ? emb1[(size_t)node * DV + d] : emb0[(size_t)c_ids[b] * DV + d];

  #pragma unroll
  for (int l = 0; l < 2; l++){
    const float* aw = attW + (size_t)(l * 3 + ntype) * 2 * DV;
    float awc = aw[d];
    float awn = aw[DV + d];
    float st0 = agg[((size_t)(l * 3 + 0) * nrows + ridx) * DV + d];
    float st1 = agg[((size_t)(l * 3 + 1) * nrows + ridx) * DV + d];
    float st2 = agg[((size_t)(l * 3 + 2) * nrows + ridx) * DV + d];
    float base = breduce128(cur * awc, sh);
    float s0 = base + breduce128(cur * awn, sh);
    float s1 = base + breduce128(st0 * awn, sh);
    float s2 = base + breduce128(st1 * awn, sh);
    float s3 = base + breduce128(st2 * awn, sh);
    float m = fmaxf(fmaxf(s0, s1), fmaxf(s2, s3));
    float e0 = expf(s0 - m), e1 = expf(s1 - m), e2 = expf(s2 - m), e3 = expf(s3 - m);
    float inv = 1.0f / (e0 + e1 + e2 + e3);
    float v = (e0 * cur + e1 * st0 + e2 * st1 + e3 * st2) * inv;
    cur = (v > 0.0f) ? v : 0.01f * v;
  }
  if (isT) g_attnT[(size_t)node * DV + d] = cur;
  else     out[(size_t)b * DV + d] = cur;
}

// Kernel 4: gather type-1 attention outputs by pos/neg ids (float4/thread).
__global__ void __launch_bounds__(256) scatter_kernel(
    const int* __restrict__ pos_ids, const int* __restrict__ neg_ids,
    float* __restrict__ out)
{
  const int i   = blockIdx.x * 256 + threadIdx.x;   // 262,144 total = exact cover
  const int q   = i & 31;
  const int b   = (i >> 5) & 4095;
  const int set = i >> 17;                          // 0 -> pos, 1 -> neg
  const int id  = set ? neg_ids[b] : pos_ids[b];
  ((float4*)out)[((size_t)(set + 1) * BSZ + b) * 32 + q] =
      ((const float4*)g_attnT)[(size_t)id * 32 + q];
}

// ---------------------------------------------------------------------------
extern "C" void kernel_launch(void* const* d_in, const int* in_sizes, int n_in,
                              void* d_out, int out_size)
{
  const int*   c_ids   = (const int*)d_in[0];
  const int*   pos_ids = (const int*)d_in[1];
  const int*   neg_ids = (const int*)d_in[2];
  const int*   n00 = (const int*)d_in[3];
  const int*   n01 = (const int*)d_in[4];
  const int*   n02 = (const int*)d_in[5];
  const int*   n10 = (const int*)d_in[6];
  const int*   n11 = (const int*)d_in[7];
  const int*   n12 = (const int*)d_in[8];
  // d_in[9..11] = neigh_s2_* (unused)
  const float* emb0 = (const float*)d_in[12];
  const float* emb1 = (const float*)d_in[13];
  const float* emb2 = (const float*)d_in[14];
  const float* Wih  = (const float*)d_in[15];
  const float* Whh  = (const float*)d_in[16];
  const float* bih  = (const float*)d_in[17];
  const float* bhh  = (const float*)d_in[18];
  const float* attW = (const float*)d_in[19];

  cudaFuncSetAttribute(precompute_P_kernel, cudaFuncAttributeMaxDynamicSharedMemorySize, P_SMEM_BYTES);
  cudaFuncSetAttribute(rnn_mma_kernel,      cudaFuncAttributeMaxDynamicSharedMemorySize, RNN_SMEM_BYTES);

  precompute_P_kernel<<<dim3(146), 512, P_SMEM_BYTES>>>(emb0, emb1, emb2, Wih, bih, bhh);
  rnn_mma_kernel<<<dim3(96, 6), 256, RNN_SMEM_BYTES>>>(Whh, c_ids,
                                                       n00, n01, n02, n10, n11, n12);
  attn_kernel<<<dim3(BSZ + T1PAD), 128>>>(emb0, emb1, c_ids, attW, (float*)d_out);
  scatter_kernel<<<dim3(1024), 256>>>(pos_ids, neg_ids, (float*)d_out);
}

// round 13
// speedup vs baseline: 1.2707x; 1.2707x over previous
#include <cuda_runtime.h>
#include <cuda_fp16.h>
#include <cstdint>

#define DV 128
#define NSTEP 10
#define BSZ 4096
#define CNT0 20000
#define CNT1 2000
#define CNT2 15000
#define ROWS_TOT (CNT0 + CNT1 + CNT2)
#define T1PAD 2048   // type-1 node count padded to tile multiple

typedef unsigned long long u64;

__device__ __align__(16) float g_P[2 * ROWS_TOT * DV];          // x@Wih^T + bih + bhh
__device__ __align__(16) float g_aggC[6 * BSZ * DV];            // c-set RNN means  [lay*3+nt][b]
__device__ __align__(16) float g_aggT[6 * T1PAD * DV];          // type-1 RNN means [lay*3+nt][node]
__device__ __align__(16) float g_attnT[T1PAD * DV];             // type-1 attention output per node

// HW tanh (sm_75+ MUFU TANH): 1 MUFU op, max rel err ~2^-11 (within budget)
static __device__ __forceinline__ float tanh_hw(float x){
  float y;
  asm("tanh.approx.f32 %0, %1;" : "=f"(y) : "f"(x));
  return y;
}
static __device__ __forceinline__ uint32_t tf32b(float v){
  uint32_t b;
  asm("cvt.rna.tf32.f32 %0, %1;" : "=r"(b) : "f"(v));
  return b;
}
static __device__ __forceinline__ uint32_t h2pack(float a, float b){
  __half2 h = __floats2half2_rn(a, b);
  return *(uint32_t*)&h;
}
// m16n8k8 tf32 HMMA (precompute kernel)
static __device__ __forceinline__ void mma_tf32(float* c,
    uint32_t a0, uint32_t a1, uint32_t a2, uint32_t a3, uint32_t b0, uint32_t b1){
  asm volatile("mma.sync.aligned.m16n8k8.row.col.f32.tf32.tf32.f32 "
    "{%0,%1,%2,%3}, {%4,%5,%6,%7}, {%8,%9}, {%0,%1,%2,%3};"
    : "+f"(c[0]), "+f"(c[1]), "+f"(c[2]), "+f"(c[3])
    : "r"(a0), "r"(a1), "r"(a2), "r"(a3), "r"(b0), "r"(b1));
}
// m16n8k16 fp16 HMMA, f32 accumulate (rnn kernel)
static __device__ __forceinline__ void mma_f16(float* c,
    uint32_t a0, uint32_t a1, uint32_t a2, uint32_t a3, uint32_t b0, uint32_t b1){
  asm volatile("mma.sync.aligned.m16n8k16.row.col.f32.f16.f16.f32 "
    "{%0,%1,%2,%3}, {%4,%5,%6,%7}, {%8,%9}, {%0,%1,%2,%3};"
    : "+f"(c[0]), "+f"(c[1]), "+f"(c[2]), "+f"(c[3])
    : "r"(a0), "r"(a1), "r"(a2), "r"(a3), "r"(b0), "r"(b1));
}

// ---------------------------------------------------------------------------
// Kernel 1 (unchanged from R9 win): P = emb @ Wih^T + biases, HMMA tf32.
// ---------------------------------------------------------------------------
#define PXB 32768
#define P_SMEM_BYTES ((32768 + 17408) * 4)

__global__ void __launch_bounds__(512, 1) precompute_P_kernel(
    const float* __restrict__ emb0, const float* __restrict__ emb1, const float* __restrict__ emb2,
    const float* __restrict__ Wih, const float* __restrict__ bih, const float* __restrict__ bhh)
{
  extern __shared__ float smf[];
  float* XB = smf + PXB;
  float* OT = smf + PXB;      // alias (phases separated by syncs)

  const int tid  = threadIdx.x;
  const int w    = tid >> 5;
  const int lane = tid & 31;
  const int g    = lane >> 2;
  const int t    = lane & 3;

  int xb = blockIdx.x, nt, tile0, rows;
  if (xb < 79)      { nt = 0; tile0 = xb * 2;        rows = CNT0; }
  else if (xb < 87) { nt = 1; tile0 = (xb - 79) * 2; rows = CNT1; }
  else              { nt = 2; tile0 = (xb - 87) * 2; rows = CNT2; }
  const float* emb = (nt == 0) ? emb0 : ((nt == 1) ? emb1 : emb2);

  for (int idx = tid; idx < 8192; idx += 512){
    int ll  = idx & 31;
    int kc  = (idx >> 5) & 15;
    int jsb = (idx >> 9) & 7;
    int lay = idx >> 12;
    const float* Wb = Wih + (size_t)(lay * 3 + nt) * DV * DV;
    int gg = ll >> 2, tt = ll & 3;
    int j = 16 * jsb + gg, k = 8 * kc + tt;
    uint4 hi;
    hi.x = tf32b(Wb[j * DV + k]);
    hi.y = tf32b(Wb[(j + 8) * DV + k]);
    hi.z = tf32b(Wb[j * DV + k + 4]);
    hi.w = tf32b(Wb[(j + 8) * DV + k + 4]);
    *(uint4*)&smf[lay * 16384 + (jsb * 16 + kc) * 128 + ll * 4] = hi;
  }

  const int js = w & 7;
  const int j0 = js << 4;
  const int m0base = (w >> 3) << 6;

  #pragma unroll
  for (int sub = 0; sub < 2; sub++){
    const int row0 = (tile0 + sub) * 128;
    if (row0 >= rows) break;

    __syncthreads();

    {
      uint32_t* XBu = (uint32_t*)XB;
      for (int idx = tid; idx < 4096; idx += 512){
        int m = idx >> 5, q = idx & 31;
        int gr = row0 + m;
        float4 v = make_float4(0.f, 0.f, 0.f, 0.f);
        if (gr < rows) v = *(const float4*)(emb + (size_t)gr * DV + 4 * q);
        const float* ve = (const float*)&v;
        #pragma unroll
        for (int e = 0; e < 4; e++){
          int k = 4 * q + e;
          XBu[((k >> 3) * 128 + m) * 8 + (k & 3) * 2 + ((k >> 2) & 1)] = tf32b(ve[e]);
        }
      }
    }
    __syncthreads();

    float c0[8][4], c1[8][4];
    #pragma unroll
    for (int mt = 0; mt < 8; mt++)
      #pragma unroll
      for (int q = 0; q < 4; q++){ c0[mt][q] = 0.0f; c1[mt][q] = 0.0f; }

    #pragma unroll 2
    for (int kc = 0; kc < 16; kc++){
      uint4 A0 = *(const uint4*)&smf[(js * 16 + kc) * 128 + lane * 4];
      uint4 A1 = *(const uint4*)&smf[16384 + (js * 16 + kc) * 128 + lane * 4];
      #pragma unroll
      for (int mt = 0; mt < 8; mt++){
        float2 b = *(const float2*)&XB[(kc * 128 + m0base + 8 * mt + g) * 8 + t * 2];
        uint32_t b0 = __float_as_uint(b.x), b1 = __float_as_uint(b.y);
        mma_tf32(c0[mt], A0.x, A0.y, A0.z, A0.w, b0, b1);
        mma_tf32(c1[mt], A1.x, A1.y, A1.z, A1.w, b0, b1);
      }
    }
    __syncthreads();

    #pragma unroll
    for (int lay = 0; lay < 2; lay++){
      const int comb = lay * 3 + nt;
      const float bj0 = bih[(size_t)comb * DV + j0 + g]     + bhh[(size_t)comb * DV + j0 + g];
      const float bj8 = bih[(size_t)comb * DV + j0 + g + 8] + bhh[(size_t)comb * DV + j0 + g + 8];
      float (*c)[4] = lay ? c1 : c0;
      #pragma unroll
      for (int mt = 0; mt < 8; mt++){
        int m0 = m0base + 8 * mt;
        OT[(m0 + 2 * t    ) * 136 + j0 + g    ] = c[mt][0] + bj0;
        OT[(m0 + 2 * t + 1) * 136 + j0 + g    ] = c[mt][1] + bj0;
        OT[(m0 + 2 * t    ) * 136 + j0 + g + 8] = c[mt][2] + bj8;
        OT[(m0 + 2 * t + 1) * 136 + j0 + g + 8] = c[mt][3] + bj8;
      }
      __syncthreads();
      const size_t Poff = (size_t)lay * ROWS_TOT * DV
                        + (size_t)((nt == 0) ? 0 : ((nt == 1) ? CNT0 : (CNT0 + CNT1))) * DV;
      for (int idx = tid; idx < 4096; idx += 512){
        int m = idx >> 5, q = idx & 31;
        int gr = row0 + m;
        if (gr < rows)
          *(float4*)(g_P + Poff + (size_t)gr * DV + 4 * q) = *(const float4*)&OT[m * 136 + 4 * q];
      }
      if (lay == 0) __syncthreads();
    }
  }
}

// ---------------------------------------------------------------------------
// Kernel 2 (R11 structure, tanh -> HW tanh.approx): fp16 m16n8k16 HMMA,
// two independent 256-thread groups with named barriers; block-wide syncs
// only around the final HT alias.
// smem: WF 32KB | HP 2x32KB | nids 5KB = 103,424 B
// ---------------------------------------------------------------------------
#define RHP_F 8192
#define RNID_F 24576
#define RNN_SMEM_BYTES ((24576 + 1280) * 4)

__global__ void __launch_bounds__(512, 1) rnn_mma_kernel(
    const float* __restrict__ Whh,
    const int* __restrict__ c_ids,
    const int* __restrict__ n00, const int* __restrict__ n01, const int* __restrict__ n02,
    const int* __restrict__ n10, const int* __restrict__ n11, const int* __restrict__ n12)
{
  extern __shared__ float smf[];
  uint4* WF4 = (uint4*)smf;                    // fp16 A fragments
  char*  HPc = (char*)(smf + RHP_F);           // 2 x 32KB fp16 h buffers
  int* nidsh = (int*)(smf + RNID_F);

  const int tid  = threadIdx.x;
  const int w    = tid >> 5;
  const int lane = tid & 31;
  const int g    = lane >> 2;
  const int t    = lane & 3;

  const int y   = blockIdx.y;       // lay*3 + nt
  const int lay = y / 3;
  const int nt  = y % 3;
  const int xb  = blockIdx.x;
  const bool isT = (xb >= 32);
  const int ntype = isT ? 1 : 0;
  const int row0  = (isT ? (xb - 32) : xb) * 128;
  const int nsel = ntype * 3 + nt;
  const int* ntab = (nsel == 0) ? n00 : (nsel == 1) ? n01 : (nsel == 2) ? n02
                  : (nsel == 3) ? n10 : (nsel == 4) ? n11 : n12;
  const float* Wb = Whh + (size_t)(lay * 3 + nt) * DV * DV;
  const float* Pb = g_P + (size_t)lay * ROWS_TOT * DV
                  + (size_t)((nt == 0) ? 0 : ((nt == 1) ? CNT0 : (CNT0 + CNT1))) * DV;

  for (int idx = tid; idx < 2048; idx += 512){
    int ll  = idx & 31;
    int kc  = (idx >> 5) & 7;
    int jsb = idx >> 8;
    int gg = ll >> 2, tt = ll & 3;
    int j = 16 * jsb + gg, k = 16 * kc + 2 * tt;
    uint4 A;
    A.x = h2pack(Wb[j * DV + k],           Wb[j * DV + k + 1]);
    A.y = h2pack(Wb[(j + 8) * DV + k],     Wb[(j + 8) * DV + k + 1]);
    A.z = h2pack(Wb[j * DV + k + 8],       Wb[j * DV + k + 9]);
    A.w = h2pack(Wb[(j + 8) * DV + k + 8], Wb[(j + 8) * DV + k + 9]);
    WF4[(jsb * 8 + kc) * 32 + ll] = A;
  }
  for (int idx = tid; idx < 128 * NSTEP; idx += 512){
    int r = idx / NSTEP, s = idx % NSTEP;
    int id = isT ? min(row0 + r, CNT1 - 1) : c_ids[row0 + r];
    nidsh[idx] = ntab[(size_t)id * NSTEP + s];
  }
  __syncthreads();   // groups independent during the recurrence loop

  const int js = w & 7;
  const int j0 = js << 4;
  const int m0base = (w >> 3) << 6;   // group 0: m 0-63, group 1: m 64-127
  const int barid = 1 + (w >> 3);

  float hsum[8][4];
  #pragma unroll
  for (int mt = 0; mt < 8; mt++)
    #pragma unroll
    for (int q = 0; q < 4; q++) hsum[mt][q] = 0.0f;

  float pf[4][4], pf2[4][4];

  for (int s = 0; s < NSTEP; s++){
    char* HPr = HPc + (((s + 1) & 1) << 15);
    char* HPw = HPc + ((s & 1) << 15);

    #pragma unroll
    for (int mt = 0; mt < 4; mt++){
      int m0 = m0base + 8 * mt;
      int nv0 = nidsh[(m0 + 2 * t) * NSTEP + s];
      int nv1 = nidsh[(m0 + 2 * t + 1) * NSTEP + s];
      const float* P0 = Pb + (size_t)nv0 * DV;
      const float* P1 = Pb + (size_t)nv1 * DV;
      pf[mt][0] = P0[j0 + g];     pf[mt][1] = P1[j0 + g];
      pf[mt][2] = P0[j0 + g + 8]; pf[mt][3] = P1[j0 + g + 8];
    }

    float c[8][4];
    #pragma unroll
    for (int mt = 0; mt < 8; mt++)
      #pragma unroll
      for (int q = 0; q < 4; q++) c[mt][q] = 0.0f;

    if (s > 0){
      #pragma unroll
      for (int kc = 0; kc < 8; kc++){
        uint4 A = WF4[(js * 8 + kc) * 32 + lane];
        #pragma unroll
        for (int mt = 0; mt < 8; mt++){
          uint2 b = *(const uint2*)(HPr + ((size_t)((kc * 128 + m0base + 8 * mt + g) * 4 + t) << 3));
          mma_f16(c[mt], A.x, A.y, A.z, A.w, b.x, b.y);
        }
      }
    }

    #pragma unroll
    for (int mt = 0; mt < 4; mt++){
      int m0 = m0base + 8 * (mt + 4);
      int nv0 = nidsh[(m0 + 2 * t) * NSTEP + s];
      int nv1 = nidsh[(m0 + 2 * t + 1) * NSTEP + s];
      const float* P0 = Pb + (size_t)nv0 * DV;
      const float* P1 = Pb + (size_t)nv1 * DV;
      pf2[mt][0] = P0[j0 + g];     pf2[mt][1] = P1[j0 + g];
      pf2[mt][2] = P0[j0 + g + 8]; pf2[mt][3] = P1[j0 + g + 8];
    }

    __half* HW = (__half*)HPw;
    #pragma unroll
    for (int mt = 0; mt < 8; mt++){
      const float* pp = (mt < 4) ? pf[mt] : pf2[mt - 4];
      int m0 = m0base + 8 * mt;
      float v0 = tanh_hw(c[mt][0] + pp[0]);   // (j0+g,   m0+2t)
      float v1 = tanh_hw(c[mt][1] + pp[1]);   // (j0+g,   m0+2t+1)
      float v2 = tanh_hw(c[mt][2] + pp[2]);   // (j0+g+8, m0+2t)
      float v3 = tanh_hw(c[mt][3] + pp[3]);   // (j0+g+8, m0+2t+1)
      hsum[mt][0] += v0; hsum[mt][1] += v1; hsum[mt][2] += v2; hsum[mt][3] += v3;
      int i0 = js * 2048 + (m0 + 2 * t) * 16 + (g >> 1) * 4 + (g & 1);
      HW[i0]      = __float2half_rn(v0);
      HW[i0 + 2]  = __float2half_rn(v2);
      HW[i0 + 16] = __float2half_rn(v1);
      HW[i0 + 18] = __float2half_rn(v3);
    }
    asm volatile("bar.sync %0, %1;" :: "r"(barid), "r"(256) : "memory");
  }

  // block-wide syncs around the HT alias (spans both groups' HP bytes)
  __syncthreads();

  float* HT = smf + RHP_F;
  const float inv = 1.0f / NSTEP;
  #pragma unroll
  for (int mt = 0; mt < 8; mt++){
    int m0 = m0base + 8 * mt;
    HT[(m0 + 2 * t    ) * 128 + j0 + g    ] = hsum[mt][0] * inv;
    HT[(m0 + 2 * t + 1) * 128 + j0 + g    ] = hsum[mt][1] * inv;
    HT[(m0 + 2 * t    ) * 128 + j0 + g + 8] = hsum[mt][2] * inv;
    HT[(m0 + 2 * t + 1) * 128 + j0 + g + 8] = hsum[mt][3] * inv;
  }
  __syncthreads();
  float* ob = isT ? (g_aggT + ((size_t)y * T1PAD + row0) * DV)
                  : (g_aggC + ((size_t)y * BSZ  + row0) * DV);
  for (int idx = tid; idx < 4096; idx += 512){
    int m = idx >> 5;
    int q = idx & 31;
    ((float4*)ob)[m * 32 + q] = *(const float4*)&HT[m * 128 + 4 * q];
  }
}

// ---------------------------------------------------------------------------
// Kernel 3: attention (deduped; unchanged).
// ---------------------------------------------------------------------------
static __device__ __forceinline__ float breduce128(float v, float* sh){
  #pragma unroll
  for (int o = 16; o > 0; o >>= 1) v += __shfl_xor_sync(0xffffffffu, v, o);
  if ((threadIdx.x & 31) == 0) sh[threadIdx.x >> 5] = v;
  __syncthreads();
  float r = sh[0] + sh[1] + sh[2] + sh[3];
  __syncthreads();
  return r;
}

__global__ void __launch_bounds__(128) attn_kernel(
    const float* __restrict__ emb0, const float* __restrict__ emb1,
    const int* __restrict__ c_ids,
    const float* __restrict__ attW, float* __restrict__ out)
{
  __shared__ float sh[4];
  const int b  = blockIdx.x;
  const int d  = threadIdx.x;
  const bool isT = (b >= BSZ);
  const int node = b - BSZ;
  if (isT && node >= CNT1) return;
  const int ntype = isT ? 1 : 0;
  const float* agg = isT ? g_aggT : g_aggC;
  const int nrows  = isT ? T1PAD : BSZ;
  const int ridx   = isT ? node : b;
  float cur = isT ? emb1[(size_t)node * DV + d] : emb0[(size_t)c_ids[b] * DV + d];

  #pragma unroll
  for (int l = 0; l < 2; l++){
    const float* aw = attW + (size_t)(l * 3 + ntype) * 2 * DV;
    float awc = aw[d];
    float awn = aw[DV + d];
    float st0 = agg[((size_t)(l * 3 + 0) * nrows + ridx) * DV + d];
    float st1 = agg[((size_t)(l * 3 + 1) * nrows + ridx) * DV + d];
    float st2 = agg[((size_t)(l * 3 + 2) * nrows + ridx) * DV + d];
    float base = breduce128(cur * awc, sh);
    float s0 = base + breduce128(cur * awn, sh);
    float s1 = base + breduce128(st0 * awn, sh);
    float s2 = base + breduce128(st1 * awn, sh);
    float s3 = base + breduce128(st2 * awn, sh);
    float m = fmaxf(fmaxf(s0, s1), fmaxf(s2, s3));
    float e0 = expf(s0 - m), e1 = expf(s1 - m), e2 = expf(s2 - m), e3 = expf(s3 - m);
    float inv = 1.0f / (e0 + e1 + e2 + e3);
    float v = (e0 * cur + e1 * st0 + e2 * st1 + e3 * st2) * inv;
    cur = (v > 0.0f) ? v : 0.01f * v;
  }
  if (isT) g_attnT[(size_t)node * DV + d] = cur;
  else     out[(size_t)b * DV + d] = cur;
}

// Kernel 4: gather type-1 attention outputs by pos/neg ids (float4/thread).
__global__ void __launch_bounds__(256) scatter_kernel(
    const int* __restrict__ pos_ids, const int* __restrict__ neg_ids,
    float* __restrict__ out)
{
  const int i   = blockIdx.x * 256 + threadIdx.x;   // 262,144 total = exact cover
  const int q   = i & 31;
  const int b   = (i >> 5) & 4095;
  const int set = i >> 17;                          // 0 -> pos, 1 -> neg
  const int id  = set ? neg_ids[b] : pos_ids[b];
  ((float4*)out)[((size_t)(set + 1) * BSZ + b) * 32 + q] =
      ((const float4*)g_attnT)[(size_t)id * 32 + q];
}

// ---------------------------------------------------------------------------
extern "C" void kernel_launch(void* const* d_in, const int* in_sizes, int n_in,
                              void* d_out, int out_size)
{
  const int*   c_ids   = (const int*)d_in[0];
  const int*   pos_ids = (const int*)d_in[1];
  const int*   neg_ids = (const int*)d_in[2];
  const int*   n00 = (const int*)d_in[3];
  const int*   n01 = (const int*)d_in[4];
  const int*   n02 = (const int*)d_in[5];
  const int*   n10 = (const int*)d_in[6];
  const int*   n11 = (const int*)d_in[7];
  const int*   n12 = (const int*)d_in[8];
  // d_in[9..11] = neigh_s2_* (unused)
  const float* emb0 = (const float*)d_in[12];
  const float* emb1 = (const float*)d_in[13];
  const float* emb2 = (const float*)d_in[14];
  const float* Wih  = (const float*)d_in[15];
  const float* Whh  = (const float*)d_in[16];
  const float* bih  = (const float*)d_in[17];
  const float* bhh  = (const float*)d_in[18];
  const float* attW = (const float*)d_in[19];

  cudaFuncSetAttribute(precompute_P_kernel, cudaFuncAttributeMaxDynamicSharedMemorySize, P_SMEM_BYTES);
  cudaFuncSetAttribute(rnn_mma_kernel,      cudaFuncAttributeMaxDynamicSharedMemorySize, RNN_SMEM_BYTES);

  precompute_P_kernel<<<dim3(146), 512, P_SMEM_BYTES>>>(emb0, emb1, emb2, Wih, bih, bhh);
  rnn_mma_kernel<<<dim3(48, 6), 512, RNN_SMEM_BYTES>>>(Whh, c_ids,
                                                       n00, n01, n02, n10, n11, n12);
  attn_kernel<<<dim3(BSZ + T1PAD), 128>>>(emb0, emb1, c_ids, attW, (float*)d_out);
  scatter_kernel<<<dim3(1024), 256>>>(pos_ids, neg_ids, (float*)d_out);
}

// round 14
// speedup vs baseline: 1.3424x; 1.0564x over previous
#include <cuda_runtime.h>
#include <cuda_fp16.h>
#include <cstdint>

#define DV 128
#define NSTEP 10
#define BSZ 4096
#define CNT0 20000
#define CNT1 2000
#define CNT2 15000
#define ROWS_TOT (CNT0 + CNT1 + CNT2)
#define T1PAD 2048   // type-1 node count padded to tile multiple

typedef unsigned long long u64;

__device__ __align__(16) __half g_P[2 * ROWS_TOT * DV];         // fp16: x@Wih^T + bih + bhh
__device__ __align__(16) float g_aggC[6 * BSZ * DV];            // c-set RNN means  [lay*3+nt][b]
__device__ __align__(16) float g_aggT[6 * T1PAD * DV];          // type-1 RNN means [lay*3+nt][node]
__device__ __align__(16) float g_attnT[T1PAD * DV];             // type-1 attention output per node

// HW tanh (sm_75+ MUFU TANH): 1 MUFU op, max rel err ~2^-11 (within budget)
static __device__ __forceinline__ float tanh_hw(float x){
  float y;
  asm("tanh.approx.f32 %0, %1;" : "=f"(y) : "f"(x));
  return y;
}
static __device__ __forceinline__ uint32_t tf32b(float v){
  uint32_t b;
  asm("cvt.rna.tf32.f32 %0, %1;" : "=r"(b) : "f"(v));
  return b;
}
static __device__ __forceinline__ uint32_t h2pack(float a, float b){
  __half2 h = __floats2half2_rn(a, b);
  return *(uint32_t*)&h;
}
// m16n8k8 tf32 HMMA (precompute kernel)
static __device__ __forceinline__ void mma_tf32(float* c,
    uint32_t a0, uint32_t a1, uint32_t a2, uint32_t a3, uint32_t b0, uint32_t b1){
  asm volatile("mma.sync.aligned.m16n8k8.row.col.f32.tf32.tf32.f32 "
    "{%0,%1,%2,%3}, {%4,%5,%6,%7}, {%8,%9}, {%0,%1,%2,%3};"
    : "+f"(c[0]), "+f"(c[1]), "+f"(c[2]), "+f"(c[3])
    : "r"(a0), "r"(a1), "r"(a2), "r"(a3), "r"(b0), "r"(b1));
}
// m16n8k16 fp16 HMMA, f32 accumulate (rnn kernel)
static __device__ __forceinline__ void mma_f16(float* c,
    uint32_t a0, uint32_t a1, uint32_t a2, uint32_t a3, uint32_t b0, uint32_t b1){
  asm volatile("mma.sync.aligned.m16n8k16.row.col.f32.f16.f16.f32 "
    "{%0,%1,%2,%3}, {%4,%5,%6,%7}, {%8,%9}, {%0,%1,%2,%3};"
    : "+f"(c[0]), "+f"(c[1]), "+f"(c[2]), "+f"(c[3])
    : "r"(a0), "r"(a1), "r"(a2), "r"(a3), "r"(b0), "r"(b1));
}

// ---------------------------------------------------------------------------
// Kernel 1: P = emb @ Wih^T + biases, HMMA tf32; OUTPUT NOW fp16.
// ---------------------------------------------------------------------------
#define PXB 32768
#define P_SMEM_BYTES ((32768 + 17408) * 4)

__global__ void __launch_bounds__(512, 1) precompute_P_kernel(
    const float* __restrict__ emb0, const float* __restrict__ emb1, const float* __restrict__ emb2,
    const float* __restrict__ Wih, const float* __restrict__ bih, const float* __restrict__ bhh)
{
  extern __shared__ float smf[];
  float* XB = smf + PXB;
  float* OT = smf + PXB;      // alias (phases separated by syncs)

  const int tid  = threadIdx.x;
  const int w    = tid >> 5;
  const int lane = tid & 31;
  const int g    = lane >> 2;
  const int t    = lane & 3;

  int xb = blockIdx.x, nt, tile0, rows;
  if (xb < 79)      { nt = 0; tile0 = xb * 2;        rows = CNT0; }
  else if (xb < 87) { nt = 1; tile0 = (xb - 79) * 2; rows = CNT1; }
  else              { nt = 2; tile0 = (xb - 87) * 2; rows = CNT2; }
  const float* emb = (nt == 0) ? emb0 : ((nt == 1) ? emb1 : emb2);

  for (int idx = tid; idx < 8192; idx += 512){
    int ll  = idx & 31;
    int kc  = (idx >> 5) & 15;
    int jsb = (idx >> 9) & 7;
    int lay = idx >> 12;
    const float* Wb = Wih + (size_t)(lay * 3 + nt) * DV * DV;
    int gg = ll >> 2, tt = ll & 3;
    int j = 16 * jsb + gg, k = 8 * kc + tt;
    uint4 hi;
    hi.x = tf32b(Wb[j * DV + k]);
    hi.y = tf32b(Wb[(j + 8) * DV + k]);
    hi.z = tf32b(Wb[j * DV + k + 4]);
    hi.w = tf32b(Wb[(j + 8) * DV + k + 4]);
    *(uint4*)&smf[lay * 16384 + (jsb * 16 + kc) * 128 + ll * 4] = hi;
  }

  const int js = w & 7;
  const int j0 = js << 4;
  const int m0base = (w >> 3) << 6;

  #pragma unroll
  for (int sub = 0; sub < 2; sub++){
    const int row0 = (tile0 + sub) * 128;
    if (row0 >= rows) break;

    __syncthreads();

    {
      uint32_t* XBu = (uint32_t*)XB;
      for (int idx = tid; idx < 4096; idx += 512){
        int m = idx >> 5, q = idx & 31;
        int gr = row0 + m;
        float4 v = make_float4(0.f, 0.f, 0.f, 0.f);
        if (gr < rows) v = *(const float4*)(emb + (size_t)gr * DV + 4 * q);
        const float* ve = (const float*)&v;
        #pragma unroll
        for (int e = 0; e < 4; e++){
          int k = 4 * q + e;
          XBu[((k >> 3) * 128 + m) * 8 + (k & 3) * 2 + ((k >> 2) & 1)] = tf32b(ve[e]);
        }
      }
    }
    __syncthreads();

    float c0[8][4], c1[8][4];
    #pragma unroll
    for (int mt = 0; mt < 8; mt++)
      #pragma unroll
      for (int q = 0; q < 4; q++){ c0[mt][q] = 0.0f; c1[mt][q] = 0.0f; }

    #pragma unroll 2
    for (int kc = 0; kc < 16; kc++){
      uint4 A0 = *(const uint4*)&smf[(js * 16 + kc) * 128 + lane * 4];
      uint4 A1 = *(const uint4*)&smf[16384 + (js * 16 + kc) * 128 + lane * 4];
      #pragma unroll
      for (int mt = 0; mt < 8; mt++){
        float2 b = *(const float2*)&XB[(kc * 128 + m0base + 8 * mt + g) * 8 + t * 2];
        uint32_t b0 = __float_as_uint(b.x), b1 = __float_as_uint(b.y);
        mma_tf32(c0[mt], A0.x, A0.y, A0.z, A0.w, b0, b1);
        mma_tf32(c1[mt], A1.x, A1.y, A1.z, A1.w, b0, b1);
      }
    }
    __syncthreads();

    #pragma unroll
    for (int lay = 0; lay < 2; lay++){
      const int comb = lay * 3 + nt;
      const float bj0 = bih[(size_t)comb * DV + j0 + g]     + bhh[(size_t)comb * DV + j0 + g];
      const float bj8 = bih[(size_t)comb * DV + j0 + g + 8] + bhh[(size_t)comb * DV + j0 + g + 8];
      float (*c)[4] = lay ? c1 : c0;
      #pragma unroll
      for (int mt = 0; mt < 8; mt++){
        int m0 = m0base + 8 * mt;
        OT[(m0 + 2 * t    ) * 136 + j0 + g    ] = c[mt][0] + bj0;
        OT[(m0 + 2 * t + 1) * 136 + j0 + g    ] = c[mt][1] + bj0;
        OT[(m0 + 2 * t    ) * 136 + j0 + g + 8] = c[mt][2] + bj8;
        OT[(m0 + 2 * t + 1) * 136 + j0 + g + 8] = c[mt][3] + bj8;
      }
      __syncthreads();
      const size_t Poff = (size_t)lay * ROWS_TOT * DV
                        + (size_t)((nt == 0) ? 0 : ((nt == 1) ? CNT0 : (CNT0 + CNT1))) * DV;
      for (int idx = tid; idx < 4096; idx += 512){
        int m = idx >> 5, q = idx & 31;
        int gr = row0 + m;
        if (gr < rows){
          float4 v = *(const float4*)&OT[m * 136 + 4 * q];
          uint2 hv;
          hv.x = h2pack(v.x, v.y);
          hv.y = h2pack(v.z, v.w);
          *(uint2*)(g_P + Poff + (size_t)gr * DV + 4 * q) = hv;
        }
      }
      if (lay == 0) __syncthreads();
    }
  }
}

// ---------------------------------------------------------------------------
// Kernel 2 (R13 structure; P gather now fp16): fp16 m16n8k16 HMMA,
// two independent 256-thread groups with named barriers.
// smem: WF 32KB | HP 2x32KB | nids 5KB = 103,424 B
// ---------------------------------------------------------------------------
#define RHP_F 8192
#define RNID_F 24576
#define RNN_SMEM_BYTES ((24576 + 1280) * 4)

__global__ void __launch_bounds__(512, 1) rnn_mma_kernel(
    const float* __restrict__ Whh,
    const int* __restrict__ c_ids,
    const int* __restrict__ n00, const int* __restrict__ n01, const int* __restrict__ n02,
    const int* __restrict__ n10, const int* __restrict__ n11, const int* __restrict__ n12)
{
  extern __shared__ float smf[];
  uint4* WF4 = (uint4*)smf;                    // fp16 A fragments
  char*  HPc = (char*)(smf + RHP_F);           // 2 x 32KB fp16 h buffers
  int* nidsh = (int*)(smf + RNID_F);

  const int tid  = threadIdx.x;
  const int w    = tid >> 5;
  const int lane = tid & 31;
  const int g    = lane >> 2;
  const int t    = lane & 3;

  const int y   = blockIdx.y;       // lay*3 + nt
  const int lay = y / 3;
  const int nt  = y % 3;
  const int xb  = blockIdx.x;
  const bool isT = (xb >= 32);
  const int ntype = isT ? 1 : 0;
  const int row0  = (isT ? (xb - 32) : xb) * 128;
  const int nsel = ntype * 3 + nt;
  const int* ntab = (nsel == 0) ? n00 : (nsel == 1) ? n01 : (nsel == 2) ? n02
                  : (nsel == 3) ? n10 : (nsel == 4) ? n11 : n12;
  const float* Wb = Whh + (size_t)(lay * 3 + nt) * DV * DV;
  const __half* Pb = g_P + (size_t)lay * ROWS_TOT * DV
                   + (size_t)((nt == 0) ? 0 : ((nt == 1) ? CNT0 : (CNT0 + CNT1))) * DV;

  for (int idx = tid; idx < 2048; idx += 512){
    int ll  = idx & 31;
    int kc  = (idx >> 5) & 7;
    int jsb = idx >> 8;
    int gg = ll >> 2, tt = ll & 3;
    int j = 16 * jsb + gg, k = 16 * kc + 2 * tt;
    uint4 A;
    A.x = h2pack(Wb[j * DV + k],           Wb[j * DV + k + 1]);
    A.y = h2pack(Wb[(j + 8) * DV + k],     Wb[(j + 8) * DV + k + 1]);
    A.z = h2pack(Wb[j * DV + k + 8],       Wb[j * DV + k + 9]);
    A.w = h2pack(Wb[(j + 8) * DV + k + 8], Wb[(j + 8) * DV + k + 9]);
    WF4[(jsb * 8 + kc) * 32 + ll] = A;
  }
  for (int idx = tid; idx < 128 * NSTEP; idx += 512){
    int r = idx / NSTEP, s = idx % NSTEP;
    int id = isT ? min(row0 + r, CNT1 - 1) : c_ids[row0 + r];
    nidsh[idx] = ntab[(size_t)id * NSTEP + s];
  }
  __syncthreads();   // groups independent during the recurrence loop

  const int js = w & 7;
  const int j0 = js << 4;
  const int m0base = (w >> 3) << 6;   // group 0: m 0-63, group 1: m 64-127
  const int barid = 1 + (w >> 3);

  float hsum[8][4];
  #pragma unroll
  for (int mt = 0; mt < 8; mt++)
    #pragma unroll
    for (int q = 0; q < 4; q++) hsum[mt][q] = 0.0f;

  float pf[4][4], pf2[4][4];

  for (int s = 0; s < NSTEP; s++){
    char* HPr = HPc + (((s + 1) & 1) << 15);
    char* HPw = HPc + ((s & 1) << 15);

    #pragma unroll
    for (int mt = 0; mt < 4; mt++){
      int m0 = m0base + 8 * mt;
      int nv0 = nidsh[(m0 + 2 * t) * NSTEP + s];
      int nv1 = nidsh[(m0 + 2 * t + 1) * NSTEP + s];
      const __half* P0 = Pb + (size_t)nv0 * DV;
      const __half* P1 = Pb + (size_t)nv1 * DV;
      pf[mt][0] = __half2float(P0[j0 + g]);     pf[mt][1] = __half2float(P1[j0 + g]);
      pf[mt][2] = __half2float(P0[j0 + g + 8]); pf[mt][3] = __half2float(P1[j0 + g + 8]);
    }

    float c[8][4];
    #pragma unroll
    for (int mt = 0; mt < 8; mt++)
      #pragma unroll
      for (int q = 0; q < 4; q++) c[mt][q] = 0.0f;

    if (s > 0){
      #pragma unroll
      for (int kc = 0; kc < 8; kc++){
        uint4 A = WF4[(js * 8 + kc) * 32 + lane];
        #pragma unroll
        for (int mt = 0; mt < 8; mt++){
          uint2 b = *(const uint2*)(HPr + ((size_t)((kc * 128 + m0base + 8 * mt + g) * 4 + t) << 3));
          mma_f16(c[mt], A.x, A.y, A.z, A.w, b.x, b.y);
        }
      }
    }

    #pragma unroll
    for (int mt = 0; mt < 4; mt++){
      int m0 = m0base + 8 * (mt + 4);
      int nv0 = nidsh[(m0 + 2 * t) * NSTEP + s];
      int nv1 = nidsh[(m0 + 2 * t + 1) * NSTEP + s];
      const __half* P0 = Pb + (size_t)nv0 * DV;
      const __half* P1 = Pb + (size_t)nv1 * DV;
      pf2[mt][0] = __half2float(P0[j0 + g]);     pf2[mt][1] = __half2float(P1[j0 + g]);
      pf2[mt][2] = __half2float(P0[j0 + g + 8]); pf2[mt][3] = __half2float(P1[j0 + g + 8]);
    }

    __half* HW = (__half*)HPw;
    #pragma unroll
    for (int mt = 0; mt < 8; mt++){
      const float* pp = (mt < 4) ? pf[mt] : pf2[mt - 4];
      int m0 = m0base + 8 * mt;
      float v0 = tanh_hw(c[mt][0] + pp[0]);   // (j0+g,   m0+2t)
      float v1 = tanh_hw(c[mt][1] + pp[1]);   // (j0+g,   m0+2t+1)
      float v2 = tanh_hw(c[mt][2] + pp[2]);   // (j0+g+8, m0+2t)
      float v3 = tanh_hw(c[mt][3] + pp[3]);   // (j0+g+8, m0+2t+1)
      hsum[mt][0] += v0; hsum[mt][1] += v1; hsum[mt][2] += v2; hsum[mt][3] += v3;
      int i0 = js * 2048 + (m0 + 2 * t) * 16 + (g >> 1) * 4 + (g & 1);
      HW[i0]      = __float2half_rn(v0);
      HW[i0 + 2]  = __float2half_rn(v2);
      HW[i0 + 16] = __float2half_rn(v1);
      HW[i0 + 18] = __float2half_rn(v3);
    }
    asm volatile("bar.sync %0, %1;" :: "r"(barid), "r"(256) : "memory");
  }

  // block-wide syncs around the HT alias (spans both groups' HP bytes)
  __syncthreads();

  float* HT = smf + RHP_F;
  const float inv = 1.0f / NSTEP;
  #pragma unroll
  for (int mt = 0; mt < 8; mt++){
    int m0 = m0base + 8 * mt;
    HT[(m0 + 2 * t    ) * 128 + j0 + g    ] = hsum[mt][0] * inv;
    HT[(m0 + 2 * t + 1) * 128 + j0 + g    ] = hsum[mt][1] * inv;
    HT[(m0 + 2 * t    ) * 128 + j0 + g + 8] = hsum[mt][2] * inv;
    HT[(m0 + 2 * t + 1) * 128 + j0 + g + 8] = hsum[mt][3] * inv;
  }
  __syncthreads();
  float* ob = isT ? (g_aggT + ((size_t)y * T1PAD + row0) * DV)
                  : (g_aggC + ((size_t)y * BSZ  + row0) * DV);
  for (int idx = tid; idx < 4096; idx += 512){
    int m = idx >> 5;
    int q = idx & 31;
    ((float4*)ob)[m * 32 + q] = *(const float4*)&HT[m * 128 + 4 * q];
  }
}

// ---------------------------------------------------------------------------
// Kernel 3: attention (deduped; unchanged).
// ---------------------------------------------------------------------------
static __device__ __forceinline__ float breduce128(float v, float* sh){
  #pragma unroll
  for (int o = 16; o > 0; o >>= 1) v += __shfl_xor_sync(0xffffffffu, v, o);
  if ((threadIdx.x & 31) == 0) sh[threadIdx.x >> 5] = v;
  __syncthreads();
  float r = sh[0] + sh[1] + sh[2] + sh[3];
  __syncthreads();
  return r;
}

__global__ void __launch_bounds__(128) attn_kernel(
    const float* __restrict__ emb0, const float* __restrict__ emb1,
    const int* __restrict__ c_ids,
    const float* __restrict__ attW, float* __restrict__ out)
{
  __shared__ float sh[4];
  const int b  = blockIdx.x;
  const int d  = threadIdx.x;
  const bool isT = (b >= BSZ);
  const int node = b - BSZ;
  if (isT && node >= CNT1) return;
  const int ntype = isT ? 1 : 0;
  const float* agg = isT ? g_aggT : g_aggC;
  const int nrows  = isT ? T1PAD : BSZ;
  const int ridx   = isT ? node : b;
  float cur = isT ? emb1[(size_t)node * DV + d] : emb0[(size_t)c_ids[b] * DV + d];

  #pragma unroll
  for (int l = 0; l < 2; l++){
    const float* aw = attW + (size_t)(l * 3 + ntype) * 2 * DV;
    float awc = aw[d];
    float awn = aw[DV + d];
    float st0 = agg[((size_t)(l * 3 + 0) * nrows + ridx) * DV + d];
    float st1 = agg[((size_t)(l * 3 + 1) * nrows + ridx) * DV + d];
    float st2 = agg[((size_t)(l * 3 + 2) * nrows + ridx) * DV + d];
    float base = breduce128(cur * awc, sh);
    float s0 = base + breduce128(cur * awn, sh);
    float s1 = base + breduce128(st0 * awn, sh);
    float s2 = base + breduce128(st1 * awn, sh);
    float s3 = base + breduce128(st2 * awn, sh);
    float m = fmaxf(fmaxf(s0, s1), fmaxf(s2, s3));
    float e0 = expf(s0 - m), e1 = expf(s1 - m), e2 = expf(s2 - m), e3 = expf(s3 - m);
    float inv = 1.0f / (e0 + e1 + e2 + e3);
    float v = (e0 * cur + e1 * st0 + e2 * st1 + e3 * st2) * inv;
    cur = (v > 0.0f) ? v : 0.01f * v;
  }
  if (isT) g_attnT[(size_t)node * DV + d] = cur;
  else     out[(size_t)b * DV + d] = cur;
}

// Kernel 4: gather type-1 attention outputs by pos/neg ids (float4/thread).
__global__ void __launch_bounds__(256) scatter_kernel(
    const int* __restrict__ pos_ids, const int* __restrict__ neg_ids,
    float* __restrict__ out)
{
  const int i   = blockIdx.x * 256 + threadIdx.x;   // 262,144 total = exact cover
  const int q   = i & 31;
  const int b   = (i >> 5) & 4095;
  const int set = i >> 17;                          // 0 -> pos, 1 -> neg
  const int id  = set ? neg_ids[b] : pos_ids[b];
  ((float4*)out)[((size_t)(set + 1) * BSZ + b) * 32 + q] =
      ((const float4*)g_attnT)[(size_t)id * 32 + q];
}

// ---------------------------------------------------------------------------
extern "C" void kernel_launch(void* const* d_in, const int* in_sizes, int n_in,
                              void* d_out, int out_size)
{
  const int*   c_ids   = (const int*)d_in[0];
  const int*   pos_ids = (const int*)d_in[1];
  const int*   neg_ids = (const int*)d_in[2];
  const int*   n00 = (const int*)d_in[3];
  const int*   n01 = (const int*)d_in[4];
  const int*   n02 = (const int*)d_in[5];
  const int*   n10 = (const int*)d_in[6];
  const int*   n11 = (const int*)d_in[7];
  const int*   n12 = (const int*)d_in[8];
  // d_in[9..11] = neigh_s2_* (unused)
  const float* emb0 = (const float*)d_in[12];
  const float* emb1 = (const float*)d_in[13];
  const float* emb2 = (const float*)d_in[14];
  const float* Wih  = (const float*)d_in[15];
  const float* Whh  = (const float*)d_in[16];
  const float* bih  = (const float*)d_in[17];
  const float* bhh  = (const float*)d_in[18];
  const float* attW = (const float*)d_in[19];

  cudaFuncSetAttribute(precompute_P_kernel, cudaFuncAttributeMaxDynamicSharedMemorySize, P_SMEM_BYTES);
  cudaFuncSetAttribute(rnn_mma_kernel,      cudaFuncAttributeMaxDynamicSharedMemorySize, RNN_SMEM_BYTES);

  precompute_P_kernel<<<dim3(146), 512, P_SMEM_BYTES>>>(emb0, emb1, emb2, Wih, bih, bhh);
  rnn_mma_kernel<<<dim3(48, 6), 512, RNN_SMEM_BYTES>>>(Whh, c_ids,
                                                       n00, n01, n02, n10, n11, n12);
  attn_kernel<<<dim3(BSZ + T1PAD), 128>>>(emb0, emb1, c_ids, attW, (float*)d_out);
  scatter_kernel<<<dim3(1024), 256>>>(pos_ids, neg_ids, (float*)d_out);
}

// round 15
// speedup vs baseline: 1.3840x; 1.0310x over previous
#include <cuda_runtime.h>
#include <cuda_fp16.h>
#include <cstdint>

#define DV 128
#define NSTEP 10
#define BSZ 4096
#define CNT0 20000
#define CNT1 2000
#define CNT2 15000
#define ROWS_TOT (CNT0 + CNT1 + CNT2)
#define T1PAD 2048   // type-1 node count padded to tile multiple

typedef unsigned long long u64;

__device__ __align__(16) __half g_P[2 * ROWS_TOT * DV];         // fp16: x@Wih^T + bih + bhh
__device__ __align__(16) float g_aggC[6 * BSZ * DV];            // c-set RNN means  [lay*3+nt][b]
__device__ __align__(16) float g_aggT[6 * T1PAD * DV];          // type-1 RNN means [lay*3+nt][node]
__device__ __align__(16) float g_attnT[T1PAD * DV];             // type-1 attention output per node

// HW tanh (sm_75+ MUFU TANH): 1 MUFU op, max rel err ~2^-11 (within budget)
static __device__ __forceinline__ float tanh_hw(float x){
  float y;
  asm("tanh.approx.f32 %0, %1;" : "=f"(y) : "f"(x));
  return y;
}
static __device__ __forceinline__ uint32_t tf32b(float v){
  uint32_t b;
  asm("cvt.rna.tf32.f32 %0, %1;" : "=r"(b) : "f"(v));
  return b;
}
static __device__ __forceinline__ uint32_t h2pack(float a, float b){
  __half2 h = __floats2half2_rn(a, b);
  return *(uint32_t*)&h;
}
// m16n8k8 tf32 HMMA (precompute kernel)
static __device__ __forceinline__ void mma_tf32(float* c,
    uint32_t a0, uint32_t a1, uint32_t a2, uint32_t a3, uint32_t b0, uint32_t b1){
  asm volatile("mma.sync.aligned.m16n8k8.row.col.f32.tf32.tf32.f32 "
    "{%0,%1,%2,%3}, {%4,%5,%6,%7}, {%8,%9}, {%0,%1,%2,%3};"
    : "+f"(c[0]), "+f"(c[1]), "+f"(c[2]), "+f"(c[3])
    : "r"(a0), "r"(a1), "r"(a2), "r"(a3), "r"(b0), "r"(b1));
}
// m16n8k16 fp16 HMMA, f32 accumulate (rnn kernel)
static __device__ __forceinline__ void mma_f16(float* c,
    uint32_t a0, uint32_t a1, uint32_t a2, uint32_t a3, uint32_t b0, uint32_t b1){
  asm volatile("mma.sync.aligned.m16n8k16.row.col.f32.f16.f16.f32 "
    "{%0,%1,%2,%3}, {%4,%5,%6,%7}, {%8,%9}, {%0,%1,%2,%3};"
    : "+f"(c[0]), "+f"(c[1]), "+f"(c[2]), "+f"(c[3])
    : "r"(a0), "r"(a1), "r"(a2), "r"(a3), "r"(b0), "r"(b1));
}

// ---------------------------------------------------------------------------
// Kernel 1 (unchanged from R14 win): P = emb @ Wih^T + biases -> fp16.
// ---------------------------------------------------------------------------
#define PXB 32768
#define P_SMEM_BYTES ((32768 + 17408) * 4)

__global__ void __launch_bounds__(512, 1) precompute_P_kernel(
    const float* __restrict__ emb0, const float* __restrict__ emb1, const float* __restrict__ emb2,
    const float* __restrict__ Wih, const float* __restrict__ bih, const float* __restrict__ bhh)
{
  extern __shared__ float smf[];
  float* XB = smf + PXB;
  float* OT = smf + PXB;      // alias (phases separated by syncs)

  const int tid  = threadIdx.x;
  const int w    = tid >> 5;
  const int lane = tid & 31;
  const int g    = lane >> 2;
  const int t    = lane & 3;

  int xb = blockIdx.x, nt, tile0, rows;
  if (xb < 79)      { nt = 0; tile0 = xb * 2;        rows = CNT0; }
  else if (xb < 87) { nt = 1; tile0 = (xb - 79) * 2; rows = CNT1; }
  else              { nt = 2; tile0 = (xb - 87) * 2; rows = CNT2; }
  const float* emb = (nt == 0) ? emb0 : ((nt == 1) ? emb1 : emb2);

  for (int idx = tid; idx < 8192; idx += 512){
    int ll  = idx & 31;
    int kc  = (idx >> 5) & 15;
    int jsb = (idx >> 9) & 7;
    int lay = idx >> 12;
    const float* Wb = Wih + (size_t)(lay * 3 + nt) * DV * DV;
    int gg = ll >> 2, tt = ll & 3;
    int j = 16 * jsb + gg, k = 8 * kc + tt;
    uint4 hi;
    hi.x = tf32b(Wb[j * DV + k]);
    hi.y = tf32b(Wb[(j + 8) * DV + k]);
    hi.z = tf32b(Wb[j * DV + k + 4]);
    hi.w = tf32b(Wb[(j + 8) * DV + k + 4]);
    *(uint4*)&smf[lay * 16384 + (jsb * 16 + kc) * 128 + ll * 4] = hi;
  }

  const int js = w & 7;
  const int j0 = js << 4;
  const int m0base = (w >> 3) << 6;

  #pragma unroll
  for (int sub = 0; sub < 2; sub++){
    const int row0 = (tile0 + sub) * 128;
    if (row0 >= rows) break;

    __syncthreads();

    {
      uint32_t* XBu = (uint32_t*)XB;
      for (int idx = tid; idx < 4096; idx += 512){
        int m = idx >> 5, q = idx & 31;
        int gr = row0 + m;
        float4 v = make_float4(0.f, 0.f, 0.f, 0.f);
        if (gr < rows) v = *(const float4*)(emb + (size_t)gr * DV + 4 * q);
        const float* ve = (const float*)&v;
        #pragma unroll
        for (int e = 0; e < 4; e++){
          int k = 4 * q + e;
          XBu[((k >> 3) * 128 + m) * 8 + (k & 3) * 2 + ((k >> 2) & 1)] = tf32b(ve[e]);
        }
      }
    }
    __syncthreads();

    float c0[8][4], c1[8][4];
    #pragma unroll
    for (int mt = 0; mt < 8; mt++)
      #pragma unroll
      for (int q = 0; q < 4; q++){ c0[mt][q] = 0.0f; c1[mt][q] = 0.0f; }

    #pragma unroll 2
    for (int kc = 0; kc < 16; kc++){
      uint4 A0 = *(const uint4*)&smf[(js * 16 + kc) * 128 + lane * 4];
      uint4 A1 = *(const uint4*)&smf[16384 + (js * 16 + kc) * 128 + lane * 4];
      #pragma unroll
      for (int mt = 0; mt < 8; mt++){
        float2 b = *(const float2*)&XB[(kc * 128 + m0base + 8 * mt + g) * 8 + t * 2];
        uint32_t b0 = __float_as_uint(b.x), b1 = __float_as_uint(b.y);
        mma_tf32(c0[mt], A0.x, A0.y, A0.z, A0.w, b0, b1);
        mma_tf32(c1[mt], A1.x, A1.y, A1.z, A1.w, b0, b1);
      }
    }
    __syncthreads();

    #pragma unroll
    for (int lay = 0; lay < 2; lay++){
      const int comb = lay * 3 + nt;
      const float bj0 = bih[(size_t)comb * DV + j0 + g]     + bhh[(size_t)comb * DV + j0 + g];
      const float bj8 = bih[(size_t)comb * DV + j0 + g + 8] + bhh[(size_t)comb * DV + j0 + g + 8];
      float (*c)[4] = lay ? c1 : c0;
      #pragma unroll
      for (int mt = 0; mt < 8; mt++){
        int m0 = m0base + 8 * mt;
        OT[(m0 + 2 * t    ) * 136 + j0 + g    ] = c[mt][0] + bj0;
        OT[(m0 + 2 * t + 1) * 136 + j0 + g    ] = c[mt][1] + bj0;
        OT[(m0 + 2 * t    ) * 136 + j0 + g + 8] = c[mt][2] + bj8;
        OT[(m0 + 2 * t + 1) * 136 + j0 + g + 8] = c[mt][3] + bj8;
      }
      __syncthreads();
      const size_t Poff = (size_t)lay * ROWS_TOT * DV
                        + (size_t)((nt == 0) ? 0 : ((nt == 1) ? CNT0 : (CNT0 + CNT1))) * DV;
      for (int idx = tid; idx < 4096; idx += 512){
        int m = idx >> 5, q = idx & 31;
        int gr = row0 + m;
        if (gr < rows){
          float4 v = *(const float4*)&OT[m * 136 + 4 * q];
          uint2 hv;
          hv.x = h2pack(v.x, v.y);
          hv.y = h2pack(v.z, v.w);
          *(uint2*)(g_P + Poff + (size_t)gr * DV + 4 * q) = hv;
        }
      }
      if (lay == 0) __syncthreads();
    }
  }
}

// ---------------------------------------------------------------------------
// Kernel 2 (R14 structure; ALL 8 P tiles prefetched at step head so every
// gather LDG is covered by the MMA phase): fp16 m16n8k16 HMMA, two
// independent 256-thread groups with named barriers.
// smem: WF 32KB | HP 2x32KB | nids 5KB = 103,424 B
// ---------------------------------------------------------------------------
#define RHP_F 8192
#define RNID_F 24576
#define RNN_SMEM_BYTES ((24576 + 1280) * 4)

__global__ void __launch_bounds__(512, 1) rnn_mma_kernel(
    const float* __restrict__ Whh,
    const int* __restrict__ c_ids,
    const int* __restrict__ n00, const int* __restrict__ n01, const int* __restrict__ n02,
    const int* __restrict__ n10, const int* __restrict__ n11, const int* __restrict__ n12)
{
  extern __shared__ float smf[];
  uint4* WF4 = (uint4*)smf;                    // fp16 A fragments
  char*  HPc = (char*)(smf + RHP_F);           // 2 x 32KB fp16 h buffers
  int* nidsh = (int*)(smf + RNID_F);

  const int tid  = threadIdx.x;
  const int w    = tid >> 5;
  const int lane = tid & 31;
  const int g    = lane >> 2;
  const int t    = lane & 3;

  const int y   = blockIdx.y;       // lay*3 + nt
  const int lay = y / 3;
  const int nt  = y % 3;
  const int xb  = blockIdx.x;
  const bool isT = (xb >= 32);
  const int ntype = isT ? 1 : 0;
  const int row0  = (isT ? (xb - 32) : xb) * 128;
  const int nsel = ntype * 3 + nt;
  const int* ntab = (nsel == 0) ? n00 : (nsel == 1) ? n01 : (nsel == 2) ? n02
                  : (nsel == 3) ? n10 : (nsel == 4) ? n11 : n12;
  const float* Wb = Whh + (size_t)(lay * 3 + nt) * DV * DV;
  const __half* Pb = g_P + (size_t)lay * ROWS_TOT * DV
                   + (size_t)((nt == 0) ? 0 : ((nt == 1) ? CNT0 : (CNT0 + CNT1))) * DV;

  for (int idx = tid; idx < 2048; idx += 512){
    int ll  = idx & 31;
    int kc  = (idx >> 5) & 7;
    int jsb = idx >> 8;
    int gg = ll >> 2, tt = ll & 3;
    int j = 16 * jsb + gg, k = 16 * kc + 2 * tt;
    uint4 A;
    A.x = h2pack(Wb[j * DV + k],           Wb[j * DV + k + 1]);
    A.y = h2pack(Wb[(j + 8) * DV + k],     Wb[(j + 8) * DV + k + 1]);
    A.z = h2pack(Wb[j * DV + k + 8],       Wb[j * DV + k + 9]);
    A.w = h2pack(Wb[(j + 8) * DV + k + 8], Wb[(j + 8) * DV + k + 9]);
    WF4[(jsb * 8 + kc) * 32 + ll] = A;
  }
  for (int idx = tid; idx < 128 * NSTEP; idx += 512){
    int r = idx / NSTEP, s = idx % NSTEP;
    int id = isT ? min(row0 + r, CNT1 - 1) : c_ids[row0 + r];
    nidsh[idx] = ntab[(size_t)id * NSTEP + s];
  }
  __syncthreads();   // groups independent during the recurrence loop

  const int js = w & 7;
  const int j0 = js << 4;
  const int m0base = (w >> 3) << 6;   // group 0: m 0-63, group 1: m 64-127
  const int barid = 1 + (w >> 3);

  float hsum[8][4];
  #pragma unroll
  for (int mt = 0; mt < 8; mt++)
    #pragma unroll
    for (int q = 0; q < 4; q++) hsum[mt][q] = 0.0f;

  for (int s = 0; s < NSTEP; s++){
    char* HPr = HPc + (((s + 1) & 1) << 15);
    char* HPw = HPc + ((s & 1) << 15);

    // prefetch ALL 8 m-tiles' P values (latency fully covered by MMA phase)
    float pf[8][4];
    #pragma unroll
    for (int mt = 0; mt < 8; mt++){
      int m0 = m0base + 8 * mt;
      int nv0 = nidsh[(m0 + 2 * t) * NSTEP + s];
      int nv1 = nidsh[(m0 + 2 * t + 1) * NSTEP + s];
      const __half* P0 = Pb + (size_t)nv0 * DV;
      const __half* P1 = Pb + (size_t)nv1 * DV;
      pf[mt][0] = __half2float(P0[j0 + g]);     pf[mt][1] = __half2float(P1[j0 + g]);
      pf[mt][2] = __half2float(P0[j0 + g + 8]); pf[mt][3] = __half2float(P1[j0 + g + 8]);
    }

    float c[8][4];
    #pragma unroll
    for (int mt = 0; mt < 8; mt++)
      #pragma unroll
      for (int q = 0; q < 4; q++) c[mt][q] = 0.0f;

    if (s > 0){
      #pragma unroll
      for (int kc = 0; kc < 8; kc++){
        uint4 A = WF4[(js * 8 + kc) * 32 + lane];
        #pragma unroll
        for (int mt = 0; mt < 8; mt++){
          uint2 b = *(const uint2*)(HPr + ((size_t)((kc * 128 + m0base + 8 * mt + g) * 4 + t) << 3));
          mma_f16(c[mt], A.x, A.y, A.z, A.w, b.x, b.y);
        }
      }
    }

    __half* HW = (__half*)HPw;
    #pragma unroll
    for (int mt = 0; mt < 8; mt++){
      int m0 = m0base + 8 * mt;
      float v0 = tanh_hw(c[mt][0] + pf[mt][0]);   // (j0+g,   m0+2t)
      float v1 = tanh_hw(c[mt][1] + pf[mt][1]);   // (j0+g,   m0+2t+1)
      float v2 = tanh_hw(c[mt][2] + pf[mt][2]);   // (j0+g+8, m0+2t)
      float v3 = tanh_hw(c[mt][3] + pf[mt][3]);   // (j0+g+8, m0+2t+1)
      hsum[mt][0] += v0; hsum[mt][1] += v1; hsum[mt][2] += v2; hsum[mt][3] += v3;
      int i0 = js * 2048 + (m0 + 2 * t) * 16 + (g >> 1) * 4 + (g & 1);
      HW[i0]      = __float2half_rn(v0);
      HW[i0 + 2]  = __float2half_rn(v2);
      HW[i0 + 16] = __float2half_rn(v1);
      HW[i0 + 18] = __float2half_rn(v3);
    }
    asm volatile("bar.sync %0, %1;" :: "r"(barid), "r"(256) : "memory");
  }

  // block-wide syncs around the HT alias (spans both groups' HP bytes)
  __syncthreads();

  float* HT = smf + RHP_F;
  const float inv = 1.0f / NSTEP;
  #pragma unroll
  for (int mt = 0; mt < 8; mt++){
    int m0 = m0base + 8 * mt;
    HT[(m0 + 2 * t    ) * 128 + j0 + g    ] = hsum[mt][0] * inv;
    HT[(m0 + 2 * t + 1) * 128 + j0 + g    ] = hsum[mt][1] * inv;
    HT[(m0 + 2 * t    ) * 128 + j0 + g + 8] = hsum[mt][2] * inv;
    HT[(m0 + 2 * t + 1) * 128 + j0 + g + 8] = hsum[mt][3] * inv;
  }
  __syncthreads();
  float* ob = isT ? (g_aggT + ((size_t)y * T1PAD + row0) * DV)
                  : (g_aggC + ((size_t)y * BSZ  + row0) * DV);
  for (int idx = tid; idx < 4096; idx += 512){
    int m = idx >> 5;
    int q = idx & 31;
    ((float4*)ob)[m * 32 + q] = *(const float4*)&HT[m * 128 + 4 * q];
  }
}

// ---------------------------------------------------------------------------
// Kernel 3: attention — ONE WARP PER ROW (lane owns 4 contiguous d's).
// All reductions are shfl trees: zero smem, zero __syncthreads.
// ---------------------------------------------------------------------------
static __device__ __forceinline__ float wredsum(float v){
  #pragma unroll
  for (int o = 16; o > 0; o >>= 1) v += __shfl_xor_sync(0xffffffffu, v, o);
  return v;
}
static __device__ __forceinline__ float dot4w(const float4 a, const float4 b){
  return wredsum(a.x * b.x + a.y * b.y + a.z * b.z + a.w * b.w);
}

__global__ void __launch_bounds__(256) attn_kernel(
    const float* __restrict__ emb0, const float* __restrict__ emb1,
    const int* __restrict__ c_ids,
    const float* __restrict__ attW, float* __restrict__ out)
{
  const int wid  = threadIdx.x >> 5;
  const int lane = threadIdx.x & 31;
  const int row  = blockIdx.x * 8 + wid;        // 0 .. BSZ+T1PAD-1
  const bool isT = (row >= BSZ);
  const int node = row - BSZ;
  if (isT && node >= CNT1) return;
  const int ntype = isT ? 1 : 0;
  const float* agg = isT ? g_aggT : g_aggC;
  const int nrows  = isT ? T1PAD : BSZ;
  const int ridx   = isT ? node : row;
  const int d4 = lane;                           // float4 index: d = 4*lane .. 4*lane+3

  float4 cur = isT ? ((const float4*)(emb1 + (size_t)node * DV))[d4]
                   : ((const float4*)(emb0 + (size_t)c_ids[row] * DV))[d4];

  #pragma unroll
  for (int l = 0; l < 2; l++){
    const float* aw = attW + (size_t)(l * 3 + ntype) * 2 * DV;
    float4 awc = ((const float4*)aw)[d4];
    float4 awn = ((const float4*)(aw + DV))[d4];
    float4 st0 = ((const float4*)(agg + ((size_t)(l * 3 + 0) * nrows + ridx) * DV))[d4];
    float4 st1 = ((const float4*)(agg + ((size_t)(l * 3 + 1) * nrows + ridx) * DV))[d4];
    float4 st2 = ((const float4*)(agg + ((size_t)(l * 3 + 2) * nrows + ridx) * DV))[d4];
    float base = dot4w(cur, awc);
    float s0 = base + dot4w(cur, awn);
    float s1 = base + dot4w(st0, awn);
    float s2 = base + dot4w(st1, awn);
    float s3 = base + dot4w(st2, awn);
    float m = fmaxf(fmaxf(s0, s1), fmaxf(s2, s3));
    float e0 = expf(s0 - m), e1 = expf(s1 - m), e2 = expf(s2 - m), e3 = expf(s3 - m);
    float inv = 1.0f / (e0 + e1 + e2 + e3);
    float4 v;
    v.x = (e0 * cur.x + e1 * st0.x + e2 * st1.x + e3 * st2.x) * inv;
    v.y = (e0 * cur.y + e1 * st0.y + e2 * st1.y + e3 * st2.y) * inv;
    v.z = (e0 * cur.z + e1 * st0.z + e2 * st1.z + e3 * st2.z) * inv;
    v.w = (e0 * cur.w + e1 * st0.w + e2 * st1.w + e3 * st2.w) * inv;
    cur.x = (v.x > 0.0f) ? v.x : 0.01f * v.x;
    cur.y = (v.y > 0.0f) ? v.y : 0.01f * v.y;
    cur.z = (v.z > 0.0f) ? v.z : 0.01f * v.z;
    cur.w = (v.w > 0.0f) ? v.w : 0.01f * v.w;
  }
  if (isT) ((float4*)(g_attnT + (size_t)node * DV))[d4] = cur;
  else     ((float4*)(out + (size_t)row * DV))[d4] = cur;
}

// Kernel 4: gather type-1 attention outputs by pos/neg ids (float4/thread).
__global__ void __launch_bounds__(256) scatter_kernel(
    const int* __restrict__ pos_ids, const int* __restrict__ neg_ids,
    float* __restrict__ out)
{
  const int i   = blockIdx.x * 256 + threadIdx.x;   // 262,144 total = exact cover
  const int q   = i & 31;
  const int b   = (i >> 5) & 4095;
  const int set = i >> 17;                          // 0 -> pos, 1 -> neg
  const int id  = set ? neg_ids[b] : pos_ids[b];
  ((float4*)out)[((size_t)(set + 1) * BSZ + b) * 32 + q] =
      ((const float4*)g_attnT)[(size_t)id * 32 + q];
}

// ---------------------------------------------------------------------------
extern "C" void kernel_launch(void* const* d_in, const int* in_sizes, int n_in,
                              void* d_out, int out_size)
{
  const int*   c_ids   = (const int*)d_in[0];
  const int*   pos_ids = (const int*)d_in[1];
  const int*   neg_ids = (const int*)d_in[2];
  const int*   n00 = (const int*)d_in[3];
  const int*   n01 = (const int*)d_in[4];
  const int*   n02 = (const int*)d_in[5];
  const int*   n10 = (const int*)d_in[6];
  const int*   n11 = (const int*)d_in[7];
  const int*   n12 = (const int*)d_in[8];
  // d_in[9..11] = neigh_s2_* (unused)
  const float* emb0 = (const float*)d_in[12];
  const float* emb1 = (const float*)d_in[13];
  const float* emb2 = (const float*)d_in[14];
  const float* Wih  = (const float*)d_in[15];
  const float* Whh  = (const float*)d_in[16];
  const float* bih  = (const float*)d_in[17];
  const float* bhh  = (const float*)d_in[18];
  const float* attW = (const float*)d_in[19];

  cudaFuncSetAttribute(precompute_P_kernel, cudaFuncAttributeMaxDynamicSharedMemorySize, P_SMEM_BYTES);
  cudaFuncSetAttribute(rnn_mma_kernel,      cudaFuncAttributeMaxDynamicSharedMemorySize, RNN_SMEM_BYTES);

  precompute_P_kernel<<<dim3(146), 512, P_SMEM_BYTES>>>(emb0, emb1, emb2, Wih, bih, bhh);
  rnn_mma_kernel<<<dim3(48, 6), 512, RNN_SMEM_BYTES>>>(Whh, c_ids,
                                                       n00, n01, n02, n10, n11, n12);
  attn_kernel<<<dim3((BSZ + T1PAD) / 8), 256>>>(emb0, emb1, c_ids, attW, (float*)d_out);
  scatter_kernel<<<dim3(1024), 256>>>(pos_ids, neg_ids, (float*)d_out);
}

// round 16
// speedup vs baseline: 1.5612x; 1.1280x over previous
#include <cuda_runtime.h>
#include <cuda_fp16.h>
#include <cstdint>

#define DV 128
#define NSTEP 10
#define BSZ 4096
#define CNT0 20000
#define CNT1 2000
#define CNT2 15000
#define ROWS_TOT (CNT0 + CNT1 + CNT2)
#define T1PAD 2048   // type-1 node count padded to tile multiple

typedef unsigned long long u64;

__device__ __align__(16) __half g_P[2 * ROWS_TOT * DV];         // fp16: x@Wih^T + bih + bhh
__device__ __align__(16) float g_aggC[6 * BSZ * DV];            // c-set RNN means  [lay*3+nt][b]
__device__ __align__(16) float g_aggT[6 * T1PAD * DV];          // type-1 RNN means [lay*3+nt][node]
__device__ __align__(16) float g_attnT[T1PAD * DV];             // type-1 attention output per node

// HW tanh (sm_75+ MUFU TANH): 1 MUFU op, max rel err ~2^-11 (within budget)
static __device__ __forceinline__ float tanh_hw(float x){
  float y;
  asm("tanh.approx.f32 %0, %1;" : "=f"(y) : "f"(x));
  return y;
}
static __device__ __forceinline__ uint32_t h2pack(float a, float b){
  __half2 h = __floats2half2_rn(a, b);
  return *(uint32_t*)&h;
}
// m16n8k16 fp16 HMMA, f32 accumulate: A 16x16 row, B 16x8 col, C 16x8 f32
static __device__ __forceinline__ void mma_f16(float* c,
    uint32_t a0, uint32_t a1, uint32_t a2, uint32_t a3, uint32_t b0, uint32_t b1){
  asm volatile("mma.sync.aligned.m16n8k16.row.col.f32.f16.f16.f32 "
    "{%0,%1,%2,%3}, {%4,%5,%6,%7}, {%8,%9}, {%0,%1,%2,%3};"
    : "+f"(c[0]), "+f"(c[1]), "+f"(c[2]), "+f"(c[3])
    : "r"(a0), "r"(a1), "r"(a2), "r"(a3), "r"(b0), "r"(b1));
}

// ---------------------------------------------------------------------------
// Kernel 1: P = emb @ Wih^T + biases -> fp16, now via fp16 m16n8k16 HMMA
// (same fragment + (k,k+4/k+8)-pair layouts as the rnn kernel).
// One block = 2 layers x 2 row-tiles.
// smem (floats): WF both layers 16384 (64KB) | XB 8192 (32KB) | OT 17408
// ---------------------------------------------------------------------------
#define PXB_F 16384
#define POT_F 24576
#define P_SMEM_BYTES ((24576 + 17408) * 4)

__global__ void __launch_bounds__(512, 1) precompute_P_kernel(
    const float* __restrict__ emb0, const float* __restrict__ emb1, const float* __restrict__ emb2,
    const float* __restrict__ Wih, const float* __restrict__ bih, const float* __restrict__ bhh)
{
  extern __shared__ float smf[];
  uint4* WF4 = (uint4*)smf;                    // [lay][jsb][kc][lane] fp16 A fragments
  uint32_t* XB32 = (uint32_t*)(smf + PXB_F);   // x pair layout (fp16)
  const uint2* XB2 = (const uint2*)XB32;
  float* OT = smf + POT_F;

  const int tid  = threadIdx.x;
  const int w    = tid >> 5;
  const int lane = tid & 31;
  const int g    = lane >> 2;
  const int t    = lane & 3;

  int xb = blockIdx.x, nt, tile0, rows;
  if (xb < 79)      { nt = 0; tile0 = xb * 2;        rows = CNT0; }
  else if (xb < 87) { nt = 1; tile0 = (xb - 79) * 2; rows = CNT1; }
  else              { nt = 2; tile0 = (xb - 87) * 2; rows = CNT2; }
  const float* emb = (nt == 0) ? emb0 : ((nt == 1) ? emb1 : emb2);

  // fp16 W fragments for BOTH layers (same builder as rnn kernel)
  for (int idx = tid; idx < 4096; idx += 512){
    int ll  = idx & 31;
    int kc  = (idx >> 5) & 7;
    int jsb = (idx >> 8) & 7;
    int lay = idx >> 11;
    const float* Wb = Wih + (size_t)(lay * 3 + nt) * DV * DV;
    int gg = ll >> 2, tt = ll & 3;
    int j = 16 * jsb + gg, k = 16 * kc + 2 * tt;
    uint4 A;
    A.x = h2pack(Wb[j * DV + k],           Wb[j * DV + k + 1]);
    A.y = h2pack(Wb[(j + 8) * DV + k],     Wb[(j + 8) * DV + k + 1]);
    A.z = h2pack(Wb[j * DV + k + 8],       Wb[j * DV + k + 9]);
    A.w = h2pack(Wb[(j + 8) * DV + k + 8], Wb[(j + 8) * DV + k + 9]);
    WF4[lay * 2048 + (jsb * 8 + kc) * 32 + ll] = A;
  }

  const int js = w & 7;
  const int j0 = js << 4;
  const int m0base = (w >> 3) << 6;

  #pragma unroll
  for (int sub = 0; sub < 2; sub++){
    const int row0 = (tile0 + sub) * 128;
    if (row0 >= rows) break;

    __syncthreads();   // prior OT/XB consumers done; WF build done (sub=0)

    // x tile -> fp16 pair layout (each float4 = 2 packed pairs)
    for (int idx = tid; idx < 4096; idx += 512){
      int m = idx >> 5, q = idx & 31;
      int gr = row0 + m;
      float4 v = make_float4(0.f, 0.f, 0.f, 0.f);
      if (gr < rows) v = *(const float4*)(emb + (size_t)gr * DV + 4 * q);
      int kc = q >> 2;
      int r16 = (q & 3) * 4;
      int word = (r16 < 8) ? 0 : 1;
      int t0 = (word ? (r16 - 8) : r16) >> 1;
      uint32_t base = (uint32_t)((kc * 128 + m) * 4);
      XB32[(base + t0    ) * 2 + word] = h2pack(v.x, v.y);
      XB32[(base + t0 + 1) * 2 + word] = h2pack(v.z, v.w);
    }
    __syncthreads();

    float c0[8][4], c1[8][4];
    #pragma unroll
    for (int mt = 0; mt < 8; mt++)
      #pragma unroll
      for (int q = 0; q < 4; q++){ c0[mt][q] = 0.0f; c1[mt][q] = 0.0f; }

    #pragma unroll
    for (int kc = 0; kc < 8; kc++){
      uint4 A0 = WF4[(js * 8 + kc) * 32 + lane];
      uint4 A1 = WF4[2048 + (js * 8 + kc) * 32 + lane];
      #pragma unroll
      for (int mt = 0; mt < 8; mt++){
        uint2 b = XB2[(kc * 128 + m0base + 8 * mt + g) * 4 + t];
        mma_f16(c0[mt], A0.x, A0.y, A0.z, A0.w, b.x, b.y);
        mma_f16(c1[mt], A1.x, A1.y, A1.z, A1.w, b.x, b.y);
      }
    }
    __syncthreads();   // XB reads done (OT region separate, but keep phases clean)

    #pragma unroll
    for (int lay = 0; lay < 2; lay++){
      const int comb = lay * 3 + nt;
      const float bj0 = bih[(size_t)comb * DV + j0 + g]     + bhh[(size_t)comb * DV + j0 + g];
      const float bj8 = bih[(size_t)comb * DV + j0 + g + 8] + bhh[(size_t)comb * DV + j0 + g + 8];
      float (*c)[4] = lay ? c1 : c0;
      #pragma unroll
      for (int mt = 0; mt < 8; mt++){
        int m0 = m0base + 8 * mt;
        OT[(m0 + 2 * t    ) * 136 + j0 + g    ] = c[mt][0] + bj0;
        OT[(m0 + 2 * t + 1) * 136 + j0 + g    ] = c[mt][1] + bj0;
        OT[(m0 + 2 * t    ) * 136 + j0 + g + 8] = c[mt][2] + bj8;
        OT[(m0 + 2 * t + 1) * 136 + j0 + g + 8] = c[mt][3] + bj8;
      }
      __syncthreads();
      const size_t Poff = (size_t)lay * ROWS_TOT * DV
                        + (size_t)((nt == 0) ? 0 : ((nt == 1) ? CNT0 : (CNT0 + CNT1))) * DV;
      for (int idx = tid; idx < 4096; idx += 512){
        int m = idx >> 5, q = idx & 31;
        int gr = row0 + m;
        if (gr < rows){
          float4 v = *(const float4*)&OT[m * 136 + 4 * q];
          uint2 hv;
          hv.x = h2pack(v.x, v.y);
          hv.y = h2pack(v.z, v.w);
          *(uint2*)(g_P + Poff + (size_t)gr * DV + 4 * q) = hv;
        }
      }
      if (lay == 0) __syncthreads();
    }
  }
}

// ---------------------------------------------------------------------------
// Kernel 2 (unchanged from R15 win): RNN via fp16 m16n8k16 HMMA, two
// independent 256-thread groups with named barriers; all 8 P tiles
// prefetched at step head.
// smem: WF 32KB | HP 2x32KB | nids 5KB = 103,424 B
// ---------------------------------------------------------------------------
#define RHP_F 8192
#define RNID_F 24576
#define RNN_SMEM_BYTES ((24576 + 1280) * 4)

__global__ void __launch_bounds__(512, 1) rnn_mma_kernel(
    const float* __restrict__ Whh,
    const int* __restrict__ c_ids,
    const int* __restrict__ n00, const int* __restrict__ n01, const int* __restrict__ n02,
    const int* __restrict__ n10, const int* __restrict__ n11, const int* __restrict__ n12)
{
  extern __shared__ float smf[];
  uint4* WF4 = (uint4*)smf;                    // fp16 A fragments
  char*  HPc = (char*)(smf + RHP_F);           // 2 x 32KB fp16 h buffers
  int* nidsh = (int*)(smf + RNID_F);

  const int tid  = threadIdx.x;
  const int w    = tid >> 5;
  const int lane = tid & 31;
  const int g    = lane >> 2;
  const int t    = lane & 3;

  const int y   = blockIdx.y;       // lay*3 + nt
  const int lay = y / 3;
  const int nt  = y % 3;
  const int xb  = blockIdx.x;
  const bool isT = (xb >= 32);
  const int ntype = isT ? 1 : 0;
  const int row0  = (isT ? (xb - 32) : xb) * 128;
  const int nsel = ntype * 3 + nt;
  const int* ntab = (nsel == 0) ? n00 : (nsel == 1) ? n01 : (nsel == 2) ? n02
                  : (nsel == 3) ? n10 : (nsel == 4) ? n11 : n12;
  const float* Wb = Whh + (size_t)(lay * 3 + nt) * DV * DV;
  const __half* Pb = g_P + (size_t)lay * ROWS_TOT * DV
                   + (size_t)((nt == 0) ? 0 : ((nt == 1) ? CNT0 : (CNT0 + CNT1))) * DV;

  for (int idx = tid; idx < 2048; idx += 512){
    int ll  = idx & 31;
    int kc  = (idx >> 5) & 7;
    int jsb = idx >> 8;
    int gg = ll >> 2, tt = ll & 3;
    int j = 16 * jsb + gg, k = 16 * kc + 2 * tt;
    uint4 A;
    A.x = h2pack(Wb[j * DV + k],           Wb[j * DV + k + 1]);
    A.y = h2pack(Wb[(j + 8) * DV + k],     Wb[(j + 8) * DV + k + 1]);
    A.z = h2pack(Wb[j * DV + k + 8],       Wb[j * DV + k + 9]);
    A.w = h2pack(Wb[(j + 8) * DV + k + 8], Wb[(j + 8) * DV + k + 9]);
    WF4[(jsb * 8 + kc) * 32 + ll] = A;
  }
  for (int idx = tid; idx < 128 * NSTEP; idx += 512){
    int r = idx / NSTEP, s = idx % NSTEP;
    int id = isT ? min(row0 + r, CNT1 - 1) : c_ids[row0 + r];
    nidsh[idx] = ntab[(size_t)id * NSTEP + s];
  }
  __syncthreads();   // groups independent during the recurrence loop

  const int js = w & 7;
  const int j0 = js << 4;
  const int m0base = (w >> 3) << 6;   // group 0: m 0-63, group 1: m 64-127
  const int barid = 1 + (w >> 3);

  float hsum[8][4];
  #pragma unroll
  for (int mt = 0; mt < 8; mt++)
    #pragma unroll
    for (int q = 0; q < 4; q++) hsum[mt][q] = 0.0f;

  for (int s = 0; s < NSTEP; s++){
    char* HPr = HPc + (((s + 1) & 1) << 15);
    char* HPw = HPc + ((s & 1) << 15);

    // prefetch ALL 8 m-tiles' P values (latency covered by MMA phase)
    float pf[8][4];
    #pragma unroll
    for (int mt = 0; mt < 8; mt++){
      int m0 = m0base + 8 * mt;
      int nv0 = nidsh[(m0 + 2 * t) * NSTEP + s];
      int nv1 = nidsh[(m0 + 2 * t + 1) * NSTEP + s];
      const __half* P0 = Pb + (size_t)nv0 * DV;
      const __half* P1 = Pb + (size_t)nv1 * DV;
      pf[mt][0] = __half2float(P0[j0 + g]);     pf[mt][1] = __half2float(P1[j0 + g]);
      pf[mt][2] = __half2float(P0[j0 + g + 8]); pf[mt][3] = __half2float(P1[j0 + g + 8]);
    }

    float c[8][4];
    #pragma unroll
    for (int mt = 0; mt < 8; mt++)
      #pragma unroll
      for (int q = 0; q < 4; q++) c[mt][q] = 0.0f;

    if (s > 0){
      #pragma unroll
      for (int kc = 0; kc < 8; kc++){
        uint4 A = WF4[(js * 8 + kc) * 32 + lane];
        #pragma unroll
        for (int mt = 0; mt < 8; mt++){
          uint2 b = *(const uint2*)(HPr + ((size_t)((kc * 128 + m0base + 8 * mt + g) * 4 + t) << 3));
          mma_f16(c[mt], A.x, A.y, A.z, A.w, b.x, b.y);
        }
      }
    }

    __half* HW = (__half*)HPw;
    #pragma unroll
    for (int mt = 0; mt < 8; mt++){
      int m0 = m0base + 8 * mt;
      float v0 = tanh_hw(c[mt][0] + pf[mt][0]);   // (j0+g,   m0+2t)
      float v1 = tanh_hw(c[mt][1] + pf[mt][1]);   // (j0+g,   m0+2t+1)
      float v2 = tanh_hw(c[mt][2] + pf[mt][2]);   // (j0+g+8, m0+2t)
      float v3 = tanh_hw(c[mt][3] + pf[mt][3]);   // (j0+g+8, m0+2t+1)
      hsum[mt][0] += v0; hsum[mt][1] += v1; hsum[mt][2] += v2; hsum[mt][3] += v3;
      int i0 = js * 2048 + (m0 + 2 * t) * 16 + (g >> 1) * 4 + (g & 1);
      HW[i0]      = __float2half_rn(v0);
      HW[i0 + 2]  = __float2half_rn(v2);
      HW[i0 + 16] = __float2half_rn(v1);
      HW[i0 + 18] = __float2half_rn(v3);
    }
    asm volatile("bar.sync %0, %1;" :: "r"(barid), "r"(256) : "memory");
  }

  // block-wide syncs around the HT alias (spans both groups' HP bytes)
  __syncthreads();

  float* HT = smf + RHP_F;
  const float inv = 1.0f / NSTEP;
  #pragma unroll
  for (int mt = 0; mt < 8; mt++){
    int m0 = m0base + 8 * mt;
    HT[(m0 + 2 * t    ) * 128 + j0 + g    ] = hsum[mt][0] * inv;
    HT[(m0 + 2 * t + 1) * 128 + j0 + g    ] = hsum[mt][1] * inv;
    HT[(m0 + 2 * t    ) * 128 + j0 + g + 8] = hsum[mt][2] * inv;
    HT[(m0 + 2 * t + 1) * 128 + j0 + g + 8] = hsum[mt][3] * inv;
  }
  __syncthreads();
  float* ob = isT ? (g_aggT + ((size_t)y * T1PAD + row0) * DV)
                  : (g_aggC + ((size_t)y * BSZ  + row0) * DV);
  for (int idx = tid; idx < 4096; idx += 512){
    int m = idx >> 5;
    int q = idx & 31;
    ((float4*)ob)[m * 32 + q] = *(const float4*)&HT[m * 128 + 4 * q];
  }
}

// ---------------------------------------------------------------------------
// Kernel 3: attention — one warp per row, shfl-tree reductions (R15 win).
// ---------------------------------------------------------------------------
static __device__ __forceinline__ float wredsum(float v){
  #pragma unroll
  for (int o = 16; o > 0; o >>= 1) v += __shfl_xor_sync(0xffffffffu, v, o);
  return v;
}
static __device__ __forceinline__ float dot4w(const float4 a, const float4 b){
  return wredsum(a.x * b.x + a.y * b.y + a.z * b.z + a.w * b.w);
}

__global__ void __launch_bounds__(256) attn_kernel(
    const float* __restrict__ emb0, const float* __restrict__ emb1,
    const int* __restrict__ c_ids,
    const float* __restrict__ attW, float* __restrict__ out)
{
  const int wid  = threadIdx.x >> 5;
  const int lane = threadIdx.x & 31;
  const int row  = blockIdx.x * 8 + wid;        // 0 .. BSZ+T1PAD-1
  const bool isT = (row >= BSZ);
  const int node = row - BSZ;
  if (isT && node >= CNT1) return;
  const int ntype = isT ? 1 : 0;
  const float* agg = isT ? g_aggT : g_aggC;
  const int nrows  = isT ? T1PAD : BSZ;
  const int ridx   = isT ? node : row;
  const int d4 = lane;

  float4 cur = isT ? ((const float4*)(emb1 + (size_t)node * DV))[d4]
                   : ((const float4*)(emb0 + (size_t)c_ids[row] * DV))[d4];

  #pragma unroll
  for (int l = 0; l < 2; l++){
    const float* aw = attW + (size_t)(l * 3 + ntype) * 2 * DV;
    float4 awc = ((const float4*)aw)[d4];
    float4 awn = ((const float4*)(aw + DV))[d4];
    float4 st0 = ((const float4*)(agg + ((size_t)(l * 3 + 0) * nrows + ridx) * DV))[d4];
    float4 st1 = ((const float4*)(agg + ((size_t)(l * 3 + 1) * nrows + ridx) * DV))[d4];
    float4 st2 = ((const float4*)(agg + ((size_t)(l * 3 + 2) * nrows + ridx) * DV))[d4];
    float base = dot4w(cur, awc);
    float s0 = base + dot4w(cur, awn);
    float s1 = base + dot4w(st0, awn);
    float s2 = base + dot4w(st1, awn);
    float s3 = base + dot4w(st2, awn);
    float m = fmaxf(fmaxf(s0, s1), fmaxf(s2, s3));
    float e0 = expf(s0 - m), e1 = expf(s1 - m), e2 = expf(s2 - m), e3 = expf(s3 - m);
    float inv = 1.0f / (e0 + e1 + e2 + e3);
    float4 v;
    v.x = (e0 * cur.x + e1 * st0.x + e2 * st1.x + e3 * st2.x) * inv;
    v.y = (e0 * cur.y + e1 * st0.y + e2 * st1.y + e3 * st2.y) * inv;
    v.z = (e0 * cur.z + e1 * st0.z + e2 * st1.z + e3 * st2.z) * inv;
    v.w = (e0 * cur.w + e1 * st0.w + e2 * st1.w + e3 * st2.w) * inv;
    cur.x = (v.x > 0.0f) ? v.x : 0.01f * v.x;
    cur.y = (v.y > 0.0f) ? v.y : 0.01f * v.y;
    cur.z = (v.z > 0.0f) ? v.z : 0.01f * v.z;
    cur.w = (v.w > 0.0f) ? v.w : 0.01f * v.w;
  }
  if (isT) ((float4*)(g_attnT + (size_t)node * DV))[d4] = cur;
  else     ((float4*)(out + (size_t)row * DV))[d4] = cur;
}

// Kernel 4: gather type-1 attention outputs by pos/neg ids (float4/thread).
__global__ void __launch_bounds__(256) scatter_kernel(
    const int* __restrict__ pos_ids, const int* __restrict__ neg_ids,
    float* __restrict__ out)
{
  const int i   = blockIdx.x * 256 + threadIdx.x;   // 262,144 total = exact cover
  const int q   = i & 31;
  const int b   = (i >> 5) & 4095;
  const int set = i >> 17;                          // 0 -> pos, 1 -> neg
  const int id  = set ? neg_ids[b] : pos_ids[b];
  ((float4*)out)[((size_t)(set + 1) * BSZ + b) * 32 + q] =
      ((const float4*)g_attnT)[(size_t)id * 32 + q];
}

// ---------------------------------------------------------------------------
extern "C" void kernel_launch(void* const* d_in, const int* in_sizes, int n_in,
                              void* d_out, int out_size)
{
  const int*   c_ids   = (const int*)d_in[0];
  const int*   pos_ids = (const int*)d_in[1];
  const int*   neg_ids = (const int*)d_in[2];
  const int*   n00 = (const int*)d_in[3];
  const int*   n01 = (const int*)d_in[4];
  const int*   n02 = (const int*)d_in[5];
  const int*   n10 = (const int*)d_in[6];
  const int*   n11 = (const int*)d_in[7];
  const int*   n12 = (const int*)d_in[8];
  // d_in[9..11] = neigh_s2_* (unused)
  const float* emb0 = (const float*)d_in[12];
  const float* emb1 = (const float*)d_in[13];
  const float* emb2 = (const float*)d_in[14];
  const float* Wih  = (const float*)d_in[15];
  const float* Whh  = (const float*)d_in[16];
  const float* bih  = (const float*)d_in[17];
  const float* bhh  = (const float*)d_in[18];
  const float* attW = (const float*)d_in[19];

  cudaFuncSetAttribute(precompute_P_kernel, cudaFuncAttributeMaxDynamicSharedMemorySize, P_SMEM_BYTES);
  cudaFuncSetAttribute(rnn_mma_kernel,      cudaFuncAttributeMaxDynamicSharedMemorySize, RNN_SMEM_BYTES);

  precompute_P_kernel<<<dim3(146), 512, P_SMEM_BYTES>>>(emb0, emb1, emb2, Wih, bih, bhh);
  rnn_mma_kernel<<<dim3(48, 6), 512, RNN_SMEM_BYTES>>>(Whh, c_ids,
                                                       n00, n01, n02, n10, n11, n12);
  attn_kernel<<<dim3((BSZ + T1PAD) / 8), 256>>>(emb0, emb1, c_ids, attW, (float*)d_out);
  scatter_kernel<<<dim3(1024), 256>>>(pos_ids, neg_ids, (float*)d_out);
}